// round 11
// baseline (speedup 1.0000x reference)
#include <cuda_runtime.h>
#include <cuda_fp16.h>
#include <cuda_bf16.h>
#include <stdint.h>
#include <math.h>

#define N_ATOMS 100000
#define M_NBR   12
#define F_DIM   64
#define C_DIM   128
#define KW      192
#define P_ROWS  (N_ATOMS * M_NBR)  // 1200000
#define BN_EPS  1e-5f
#define NCTILES (P_ROWS / 128)     // 9375 CTA tiles of 128 rows

typedef unsigned long long u64;

// ---------------- scratch ----------------
__device__ __align__(256) float  g_S [N_ATOMS * C_DIM];
__device__ __align__(256) float  g_P [N_ATOMS * C_DIM];
__device__ __align__(256) __half g_Zh[(size_t)P_ROWS * C_DIM];
__device__ __align__(256) float  g_NS[N_ATOMS * F_DIM];
__device__ __align__(256) __nv_bfloat16 g_Wh[C_DIM * 64];   // W_edge hi (bf16)
__device__ __align__(256) __nv_bfloat16 g_Wl[C_DIM * 64];   // W_edge lo (bf16)
__device__ float g_stats1[2 * C_DIM];
__device__ float g_stats2[2 * F_DIM];
__device__ float g_aff1 [2 * C_DIM];
__device__ float g_aff2 [2 * F_DIM];

// ---------------- helpers ----------------
__device__ __forceinline__ u64 pack2(float lo, float hi) {
    u64 r; asm("mov.b64 %0, {%1, %2};" : "=l"(r) : "r"(__float_as_uint(lo)), "r"(__float_as_uint(hi))); return r;
}
__device__ __forceinline__ u64 dup2(float a) {
    u64 r; unsigned int u = __float_as_uint(a);
    asm("mov.b64 %0, {%1, %1};" : "=l"(r) : "r"(u)); return r;
}
__device__ __forceinline__ u64 ffma2(u64 a, u64 b, u64 c) {
    u64 d; asm("fma.rn.f32x2 %0, %1, %2, %3;" : "=l"(d) : "l"(a), "l"(b), "l"(c)); return d;
}
__device__ __forceinline__ float tanh_fast(float x) {
    float y; asm("tanh.approx.f32 %0, %1;" : "=f"(y) : "f"(x)); return y;
}
__device__ __forceinline__ float sigmoid_fast(float x) {
    return fmaf(0.5f, tanh_fast(0.5f * x), 0.5f);
}
__device__ __forceinline__ float softplus_fast(float x) {
    return fmaxf(x, 0.f) + __logf(1.f + __expf(-fabsf(x)));
}
__device__ __forceinline__ uint32_t smem_u32(const void* p) {
    uint32_t a;
    asm("{ .reg .u64 t; cvta.to.shared.u64 t, %1; cvt.u32.u64 %0, t; }" : "=r"(a) : "l"(p));
    return a;
}
#define SWZ(b) ((b) ^ (((b) >> 3) & 0x70))

__device__ __forceinline__ void ldsm4(uint32_t* r, uint32_t addr) {
    asm volatile("ldmatrix.sync.aligned.m8n8.x4.shared.b16 {%0,%1,%2,%3}, [%4];"
        : "=r"(r[0]), "=r"(r[1]), "=r"(r[2]), "=r"(r[3]) : "r"(addr));
}
__device__ __forceinline__ void mma_bf16(float* d, const uint32_t* a, const uint32_t* b) {
    asm volatile("mma.sync.aligned.m16n8k16.row.col.f32.bf16.bf16.f32 "
        "{%0,%1,%2,%3}, {%4,%5,%6,%7}, {%8,%9}, {%0,%1,%2,%3};"
        : "+f"(d[0]), "+f"(d[1]), "+f"(d[2]), "+f"(d[3])
        : "r"(a[0]), "r"(a[1]), "r"(a[2]), "r"(a[3]), "r"(b[0]), "r"(b[1]));
}

// k2 smem layout (dynamic, 50KB)
//   SM_A  : A-stage 128 rows x 128B (SW128)        = 16KB
//   SM_E  : E stage 64 rows x 128 ch f32 (XOR-swz) = 32KB  (also B-staging at startup)
//   SM_ST : stats scratch 512 f32                  = 2KB
#define SM_A   0
#define SM_E   16384
#define SM_BH  16384
#define SM_BL  32768
#define SM_ST  49152
#define SM_TOT 51200

// ---------------- K0: zero stats + split W_edge to bf16 hi/lo --------------
__global__ void k0_zero(const float* __restrict__ W) {
    int t = blockIdx.x * blockDim.x + threadIdx.x;
    if (t < 2 * C_DIM) g_stats1[t] = 0.f;
    if (t < 2 * F_DIM) g_stats2[t] = 0.f;
    for (int i = t; i < C_DIM * 64; i += gridDim.x * blockDim.x) {
        int c = i >> 6, k = i & 63;
        float x = W[c * KW + 128 + k];
        __nv_bfloat16 hi = __float2bfloat16(x);
        __nv_bfloat16 lo = __float2bfloat16(x - __bfloat162float(hi));
        g_Wh[i] = hi; g_Wl[i] = lo;
    }
}

__global__ void knop() {}

// ---------------- K1: S, P precompute (FFMA2 path) ----------------
__global__ __launch_bounds__(128, 4) void k1_selfnbr(
        const float* __restrict__ atom, const float* __restrict__ W,
        const float* __restrict__ b) {
    __shared__ __align__(16) float sW[64 * 128];
    __shared__ __align__(16) float sA[64 * 36];
    const int tid = threadIdx.x;
    const int n0  = blockIdx.x * 32;
    for (int i = tid; i < 32 * 64; i += 128) {
        int r = i >> 6, k = i & 63;
        sA[k * 36 + r] = atom[(n0 + r) * 64 + k];
    }
    const int rg = tid >> 4, cg = tid & 15;
    const int r0 = rg * 4,  c0 = cg * 8;
    for (int half = 0; half < 2; ++half) {
        __syncthreads();
        for (int i = tid; i < 64 * 128; i += 128) {
            int c = i >> 6, k = i & 63;
            sW[k * 128 + c] = W[c * KW + half * 64 + k];
        }
        __syncthreads();
        u64 acc[4][4];
        #pragma unroll
        for (int r = 0; r < 4; r++)
            #pragma unroll
            for (int cp = 0; cp < 4; cp++)
                acc[r][cp] = (half == 0) ? pack2(b[c0 + 2*cp], b[c0 + 2*cp + 1]) : 0ULL;
        #pragma unroll 8
        for (int k = 0; k < 64; ++k) {
            float4 av = *(const float4*)&sA[k * 36 + r0];
            ulonglong2 w0 = *(const ulonglong2*)&sW[k * 128 + c0];
            ulonglong2 w1 = *(const ulonglong2*)&sW[k * 128 + c0 + 4];
            u64 ad[4] = {dup2(av.x), dup2(av.y), dup2(av.z), dup2(av.w)};
            u64 wp[4] = {w0.x, w0.y, w1.x, w1.y};
            #pragma unroll
            for (int r = 0; r < 4; r++)
                #pragma unroll
                for (int cp = 0; cp < 4; cp++)
                    acc[r][cp] = ffma2(ad[r], wp[cp], acc[r][cp]);
        }
        float* dst = (half == 0) ? g_S : g_P;
        #pragma unroll
        for (int r = 0; r < 4; r++) {
            int n = n0 + r0 + r;
            ulonglong2 q0, q1;
            q0.x = acc[r][0]; q0.y = acc[r][1];
            q1.x = acc[r][2]; q1.y = acc[r][3];
            *(ulonglong2*)&dst[n * C_DIM + c0]     = q0;
            *(ulonglong2*)&dst[n * C_DIM + c0 + 4] = q1;
        }
    }
}

// ---------------- K2: HMMA, warp-per-channel-slice, persistent B frags -----
__global__ __launch_bounds__(128, 2) void k2_hmma(
        const float* __restrict__ nbr, const int* __restrict__ idx) {
    extern __shared__ __align__(1024) unsigned char SB[];
    const uint32_t sbase = smem_u32(SB);
    const int tid = threadIdx.x, wid = tid >> 5, lane = tid & 31;

    // stage W hi/lo into SM_BH/SM_BL (SW128 rows of 128B)
    for (int i = tid; i < 128 * 8; i += 128) {
        int c = i >> 3, u = i & 7;
        uint32_t sw = SWZ((uint32_t)(c * 128 + u * 16));
        *(uint4*)(SB + SM_BH + sw) = *(const uint4*)&g_Wh[c * 64 + u * 8];
        *(uint4*)(SB + SM_BL + sw) = *(const uint4*)&g_Wl[c * 64 + u * 8];
    }
    __syncthreads();

    const int sel  = lane >> 3;
    const int g    = lane >> 2, cq = lane & 3;
    const int rsel = ((sel & 1) << 3) | (lane & 7);   // A frag row-in-16
    const int ksel = (sel >> 1) << 4;                 // A frag k byte 0/16
    const int nsel = ((sel >> 1) << 3) | (lane & 7);  // B frag n-in-16
    const int kselB = (sel & 1) << 4;                 // B frag k byte 0/16

    // preload this warp's B fragments (channels wid*32 .. +31) — loop-invariant
    uint32_t Bf[4][2][2][4];   // [ks][q2][hi/lo][4]
    #pragma unroll
    for (int ks = 0; ks < 4; ++ks)
        #pragma unroll
        for (int q2 = 0; q2 < 2; ++q2) {
            uint32_t byteB = (uint32_t)((wid * 32 + q2 * 16 + nsel) * 128 + ks * 32 + kselB);
            ldsm4(Bf[ks][q2][0], sbase + SM_BH + SWZ(byteB));
            ldsm4(Bf[ks][q2][1], sbase + SM_BL + SWZ(byteB));
        }
    __syncthreads();   // done with B staging; SM_E region is now free

    const int cb = tid & 7;       // epilogue channel block (16 ch)
    const int rt = tid >> 3;      // epilogue row-in-16
    float lsum[16], lsq[16];
    #pragma unroll
    for (int e = 0; e < 16; ++e) { lsum[e] = 0.f; lsq[e] = 0.f; }

    for (int tile = blockIdx.x; tile < NCTILES; tile += gridDim.x) {
        const int p0 = tile * 128;

        // stage A: 128 rows x 64 f32 -> bf16 hi, SW128
        #pragma unroll
        for (int pp = 0; pp < 4; ++pp) {
            int r  = pp * 32 + (tid >> 2);
            int c0 = (tid & 3) * 16;
            #pragma unroll
            for (int q = 0; q < 4; ++q) {
                float4 v = __ldcs((const float4*)&nbr[(size_t)(p0 + r) * 64 + c0 + q * 4]);
                __nv_bfloat162 h0, h1;
                h0.x = __float2bfloat16(v.x); h0.y = __float2bfloat16(v.y);
                h1.x = __float2bfloat16(v.z); h1.y = __float2bfloat16(v.w);
                uint32_t sw = SWZ((uint32_t)(r * 128 + (c0 + q * 4) * 2));
                uint2 sh; sh.x = *(uint32_t*)&h0; sh.y = *(uint32_t*)&h1;
                *(uint2*)(SB + SM_A + sw) = sh;
            }
        }
        __syncthreads();

        #pragma unroll
        for (int half = 0; half < 2; ++half) {
            float acc[4][4][4];   // [mf rows][nf = q2*2+b][4]
            #pragma unroll
            for (int mf = 0; mf < 4; ++mf)
                #pragma unroll
                for (int nf = 0; nf < 4; ++nf)
                    #pragma unroll
                    for (int e = 0; e < 4; ++e) acc[mf][nf][e] = 0.f;

            #pragma unroll
            for (int ks = 0; ks < 4; ++ks) {
                uint32_t Af[4][4];
                #pragma unroll
                for (int mf = 0; mf < 4; ++mf) {
                    uint32_t byteA = (uint32_t)((half * 64 + mf * 16 + rsel) * 128 + ks * 32 + ksel);
                    ldsm4(Af[mf], sbase + SM_A + SWZ(byteA));
                }
                #pragma unroll
                for (int mf = 0; mf < 4; ++mf)
                    #pragma unroll
                    for (int q2 = 0; q2 < 2; ++q2) {
                        mma_bf16(acc[mf][q2*2],   Af[mf], Bf[ks][q2][0]);
                        mma_bf16(acc[mf][q2*2],   Af[mf], Bf[ks][q2][1]);
                        mma_bf16(acc[mf][q2*2+1], Af[mf], &Bf[ks][q2][0][2]);
                        mma_bf16(acc[mf][q2*2+1], Af[mf], &Bf[ks][q2][1][2]);
                    }
            }

            // stage acc -> E (64 rows x 128 ch f32, XOR-unit swizzle)
            #pragma unroll
            for (int mf = 0; mf < 4; ++mf)
                #pragma unroll
                for (int nf = 0; nf < 4; ++nf)
                    #pragma unroll
                    for (int rr = 0; rr < 2; ++rr) {
                        int r = mf * 16 + rr * 8 + g;
                        int c = wid * 32 + (nf >> 1) * 16 + (nf & 1) * 8 + cq * 2;
                        uint32_t unit = ((uint32_t)r << 5) + (((uint32_t)c >> 2) ^ ((uint32_t)r & 31));
                        uint32_t addr = sbase + SM_E + (unit << 4) + ((uint32_t)(c & 3) << 2);
                        asm volatile("st.shared.v2.f32 [%0], {%1, %2};" ::
                            "r"(addr), "f"(acc[mf][nf][rr*2]), "f"(acc[mf][nf][rr*2+1]));
                    }
            __syncthreads();

            // epilogue: thread -> row pass*16+rt, channels cb*16..+15
            #pragma unroll
            for (int pass = 0; pass < 4; ++pass) {
                int r = pass * 16 + rt;
                int p = p0 + half * 64 + r;
                int n = p / 12;
                int j = __ldg(&idx[p]);
                float z[16];
                #pragma unroll
                for (int u = 0; u < 4; ++u) {
                    uint32_t cu = (uint32_t)(cb * 4 + u);
                    uint32_t unit = ((uint32_t)r << 5) + (cu ^ ((uint32_t)r & 31));
                    float ex, ey, ez, ew;
                    asm volatile("ld.shared.v4.f32 {%0,%1,%2,%3}, [%4];"
                        : "=f"(ex), "=f"(ey), "=f"(ez), "=f"(ew)
                        : "r"(sbase + SM_E + (unit << 4)));
                    float4 s  = *(const float4*)&g_S[(size_t)n * C_DIM + cb * 16 + u * 4];
                    float4 pv = *(const float4*)&g_P[(size_t)j * C_DIM + cb * 16 + u * 4];
                    z[u*4+0] = ex + s.x + pv.x;
                    z[u*4+1] = ey + s.y + pv.y;
                    z[u*4+2] = ez + s.z + pv.z;
                    z[u*4+3] = ew + s.w + pv.w;
                }
                #pragma unroll
                for (int e = 0; e < 16; ++e) {
                    lsum[e] += z[e];
                    lsq[e]  = fmaf(z[e], z[e], lsq[e]);
                }
                uint4 st0, st1;
                {
                    __half2 a0 = __floats2half2_rn(z[0],  z[1]);
                    __half2 a1 = __floats2half2_rn(z[2],  z[3]);
                    __half2 a2 = __floats2half2_rn(z[4],  z[5]);
                    __half2 a3 = __floats2half2_rn(z[6],  z[7]);
                    __half2 a4 = __floats2half2_rn(z[8],  z[9]);
                    __half2 a5 = __floats2half2_rn(z[10], z[11]);
                    __half2 a6 = __floats2half2_rn(z[12], z[13]);
                    __half2 a7 = __floats2half2_rn(z[14], z[15]);
                    st0.x = *(uint32_t*)&a0; st0.y = *(uint32_t*)&a1;
                    st0.z = *(uint32_t*)&a2; st0.w = *(uint32_t*)&a3;
                    st1.x = *(uint32_t*)&a4; st1.y = *(uint32_t*)&a5;
                    st1.z = *(uint32_t*)&a6; st1.w = *(uint32_t*)&a7;
                }
                __stcs((uint4*)&g_Zh[(size_t)p * C_DIM + cb * 16],     st0);
                __stcs((uint4*)&g_Zh[(size_t)p * C_DIM + cb * 16 + 8], st1);
            }
            __syncthreads();   // E (and A, at loop top) reuse guard
        }
    }

    // ---- CTA-level stats reduction ----
    float* st = (float*)(SB + SM_ST);   // 512 floats: [sum 256][sq 256] (128 used each)
    for (int i = tid; i < 512; i += 128) st[i] = 0.f;
    __syncthreads();
    #pragma unroll
    for (int e = 0; e < 16; ++e) {
        int ch = cb * 16 + e;
        atomicAdd(&st[ch],       lsum[e]);
        atomicAdd(&st[256 + ch], lsq[e]);
    }
    __syncthreads();
    if (tid < 128) {
        atomicAdd(&g_stats1[tid],       st[tid]);
        atomicAdd(&g_stats1[128 + tid], st[256 + tid]);
    }
}

// ---------------- K3 ----------------
__global__ void k3_aff1(const float* __restrict__ gamma1,
                        const float* __restrict__ beta1) {
    int c = threadIdx.x;
    float inv  = 1.f / (float)P_ROWS;
    float mean = g_stats1[c] * inv;
    float var  = g_stats1[128 + c] * inv - mean * mean;
    float sc   = gamma1[c] * rsqrtf(var + BN_EPS);
    g_aff1[c]       = sc;
    g_aff1[128 + c] = beta1[c] - mean * sc;
}

// ---------------- K4 ----------------
__global__ __launch_bounds__(256) void k4_reduce(const float* __restrict__ bw) {
    __shared__ float sSum[64], sSq[64];
    const int tid = threadIdx.x;
    if (tid < 64) { sSum[tid] = 0.f; sSq[tid] = 0.f; }
    __syncthreads();
    const int f2 = (tid & 31) * 2;
    const int al = tid >> 5;
    const float sc1a = g_aff1[f2],        sh1a = g_aff1[128 + f2];
    const float sc1b = g_aff1[f2 + 1],    sh1b = g_aff1[128 + f2 + 1];
    const float sc2a = g_aff1[64 + f2],   sh2a = g_aff1[192 + f2];
    const float sc2b = g_aff1[64 + f2+1], sh2b = g_aff1[192 + f2 + 1];
    float lsa = 0.f, lqa = 0.f, lsb = 0.f, lqb = 0.f;
    for (int n = blockIdx.x * 8 + al; n < N_ATOMS; n += gridDim.x * 8) {
        float acca = 0.f, accb = 0.f;
        #pragma unroll
        for (int m = 0; m < 12; m++) {
            size_t base = (size_t)(n * 12 + m) * C_DIM;
            float2 v1 = __half22float2(*(const __half2*)&g_Zh[base + f2]);
            float2 v2 = __half22float2(*(const __half2*)&g_Zh[base + 64 + f2]);
            float z1a = fmaf(v1.x, sc1a, sh1a);
            float z1b = fmaf(v1.y, sc1b, sh1b);
            float z2a = fmaf(v2.x, sc2a, sh2a);
            float z2b = fmaf(v2.y, sc2b, sh2b);
            float w  = __ldg(&bw[n * 12 + m]);
            float w2 = w * w;
            acca = fmaf(w2 * sigmoid_fast(z1a), softplus_fast(z2a), acca);
            accb = fmaf(w2 * sigmoid_fast(z1b), softplus_fast(z2b), accb);
        }
        *(float2*)&g_NS[n * 64 + f2] = make_float2(acca, accb);
        lsa += acca; lqa = fmaf(acca, acca, lqa);
        lsb += accb; lqb = fmaf(accb, accb, lqb);
    }
    atomicAdd(&sSum[f2],     lsa);
    atomicAdd(&sSum[f2 + 1], lsb);
    atomicAdd(&sSq[f2],      lqa);
    atomicAdd(&sSq[f2 + 1],  lqb);
    __syncthreads();
    if (tid < 64) {
        atomicAdd(&g_stats2[tid],      sSum[tid]);
        atomicAdd(&g_stats2[64 + tid], sSq[tid]);
    }
}

// ---------------- K5 ----------------
__global__ void k5_aff2(const float* __restrict__ gamma2,
                        const float* __restrict__ beta2) {
    int f = threadIdx.x;
    float inv  = 1.f / (float)N_ATOMS;
    float mean = g_stats2[f] * inv;
    float var  = g_stats2[64 + f] * inv - mean * mean;
    float sc   = gamma2[f] * rsqrtf(var + BN_EPS);
    g_aff2[f]      = sc;
    g_aff2[64 + f] = beta2[f] - mean * sc;
}

// ---------------- K6 ----------------
__global__ void k6_out(const float* __restrict__ atom, float* __restrict__ out) {
    int i = blockIdx.x * blockDim.x + threadIdx.x;
    if (i < N_ATOMS * F_DIM) {
        int f = i & 63;
        float x = atom[i] + fmaf(g_NS[i], g_aff2[f], g_aff2[64 + f]);
        out[i] = softplus_fast(x);
    }
}

// ---------------- launch ----------------
extern "C" void kernel_launch(void* const* d_in, const int* in_sizes, int n_in,
                              void* d_out, int out_size) {
    const float* atom   = (const float*)d_in[0];
    const float* nbr    = (const float*)d_in[1];
    const float* bw     = (const float*)d_in[2];
    const int*   idx    = (const int*)  d_in[3];
    const float* W      = (const float*)d_in[4];
    const float* b      = (const float*)d_in[5];
    const float* gamma1 = (const float*)d_in[6];
    const float* beta1  = (const float*)d_in[7];
    const float* gamma2 = (const float*)d_in[8];
    const float* beta2  = (const float*)d_in[9];
    float* out = (float*)d_out;

    cudaFuncSetAttribute(k2_hmma, cudaFuncAttributeMaxDynamicSharedMemorySize, SM_TOT);

    k0_zero<<<2, 256>>>(W);
    k1_selfnbr<<<N_ATOMS / 32, 128>>>(atom, W, b);
    knop<<<1, 32>>>();
    k2_hmma<<<296, 128, SM_TOT>>>(nbr, idx);
    k3_aff1<<<1, 128>>>(gamma1, beta1);
    k4_reduce<<<592, 256>>>(bw);
    k5_aff2<<<1, 64>>>(gamma2, beta2);
    k6_out<<<(N_ATOMS * F_DIM + 255) / 256, 256>>>(atom, out);
}

// round 12
// speedup vs baseline: 1.1229x; 1.1229x over previous
#include <cuda_runtime.h>
#include <cuda_fp16.h>
#include <cuda_bf16.h>
#include <stdint.h>
#include <math.h>

#define N_ATOMS 100000
#define M_NBR   12
#define F_DIM   64
#define C_DIM   128
#define KW      192
#define P_ROWS  (N_ATOMS * M_NBR)  // 1200000
#define BN_EPS  1e-5f
#define NWTILES (P_ROWS / 32)      // 37500 warp-tiles of 32 rows

typedef unsigned long long u64;

// ---------------- scratch ----------------
__device__ __align__(256) float  g_S [N_ATOMS * C_DIM];
__device__ __align__(256) float  g_P [N_ATOMS * C_DIM];
__device__ __align__(256) __half g_Zh[(size_t)P_ROWS * C_DIM];
__device__ __align__(256) float  g_NS[N_ATOMS * F_DIM];
__device__ __align__(256) __nv_bfloat16 g_Wh[C_DIM * 64];
__device__ __align__(256) __nv_bfloat16 g_Wl[C_DIM * 64];
__device__ float g_stats1[2 * C_DIM];
__device__ float g_stats2[2 * F_DIM];
__device__ float g_aff1 [2 * C_DIM];
__device__ float g_aff2 [2 * F_DIM];

// ---------------- helpers ----------------
__device__ __forceinline__ u64 pack2(float lo, float hi) {
    u64 r; asm("mov.b64 %0, {%1, %2};" : "=l"(r) : "r"(__float_as_uint(lo)), "r"(__float_as_uint(hi))); return r;
}
__device__ __forceinline__ u64 dup2(float a) {
    u64 r; unsigned int u = __float_as_uint(a);
    asm("mov.b64 %0, {%1, %1};" : "=l"(r) : "r"(u)); return r;
}
__device__ __forceinline__ u64 ffma2(u64 a, u64 b, u64 c) {
    u64 d; asm("fma.rn.f32x2 %0, %1, %2, %3;" : "=l"(d) : "l"(a), "l"(b), "l"(c)); return d;
}
__device__ __forceinline__ float tanh_fast(float x) {
    float y; asm("tanh.approx.f32 %0, %1;" : "=f"(y) : "f"(x)); return y;
}
__device__ __forceinline__ float sigmoid_fast(float x) {
    return fmaf(0.5f, tanh_fast(0.5f * x), 0.5f);
}
__device__ __forceinline__ float softplus_fast(float x) {
    return fmaxf(x, 0.f) + __logf(1.f + __expf(-fabsf(x)));
}
__device__ __forceinline__ uint32_t smem_u32(const void* p) {
    uint32_t a;
    asm("{ .reg .u64 t; cvta.to.shared.u64 t, %1; cvt.u32.u64 %0, t; }" : "=r"(a) : "l"(p));
    return a;
}
#define SWZ(b) ((b) ^ (((b) >> 3) & 0x70))

__device__ __forceinline__ void ldsm4(uint32_t* r, uint32_t addr) {
    asm volatile("ldmatrix.sync.aligned.m8n8.x4.shared.b16 {%0,%1,%2,%3}, [%4];"
        : "=r"(r[0]), "=r"(r[1]), "=r"(r[2]), "=r"(r[3]) : "r"(addr));
}
__device__ __forceinline__ void mma_bf16(float* d, const uint32_t* a, const uint32_t* b) {
    asm volatile("mma.sync.aligned.m16n8k16.row.col.f32.bf16.bf16.f32 "
        "{%0,%1,%2,%3}, {%4,%5,%6,%7}, {%8,%9}, {%0,%1,%2,%3};"
        : "+f"(d[0]), "+f"(d[1]), "+f"(d[2]), "+f"(d[3])
        : "r"(a[0]), "r"(a[1]), "r"(a[2]), "r"(a[3]), "r"(b[0]), "r"(b[1]));
}

// k2 smem layout (dynamic, 80KB) — R10 layout
#define SM_B_HI 0
#define SM_B_LO 16384
#define SM_A_HI 32768
#define SM_E    49152
#define SM_TOT  81920

// ---------------- K1: zero stats + W split (block 0) + S,P precompute -----
__global__ __launch_bounds__(128, 4) void k1_selfnbr(
        const float* __restrict__ atom, const float* __restrict__ W,
        const float* __restrict__ b) {
    __shared__ __align__(16) float sW[64 * 128];
    __shared__ __align__(16) float sA[64 * 36];
    const int tid = threadIdx.x;
    const int n0  = blockIdx.x * 32;

    if (blockIdx.x == 0) {
        // zero stats
        if (tid < 128) { g_stats1[tid] = 0.f; g_stats1[128 + tid] = 0.f; }
        if (tid < 64)  { g_stats2[tid] = 0.f; g_stats2[64  + tid] = 0.f; }
        // split W_edge to bf16 hi/lo
        for (int i = tid; i < C_DIM * 64; i += 128) {
            int c = i >> 6, k = i & 63;
            float x = W[c * KW + 128 + k];
            __nv_bfloat16 hi = __float2bfloat16(x);
            __nv_bfloat16 lo = __float2bfloat16(x - __bfloat162float(hi));
            g_Wh[i] = hi; g_Wl[i] = lo;
        }
    }

    for (int i = tid; i < 32 * 64; i += 128) {
        int r = i >> 6, k = i & 63;
        sA[k * 36 + r] = atom[(n0 + r) * 64 + k];
    }
    const int rg = tid >> 4, cg = tid & 15;
    const int r0 = rg * 4,  c0 = cg * 8;
    for (int half = 0; half < 2; ++half) {
        __syncthreads();
        for (int i = tid; i < 64 * 128; i += 128) {
            int c = i >> 6, k = i & 63;
            sW[k * 128 + c] = W[c * KW + half * 64 + k];
        }
        __syncthreads();
        u64 acc[4][4];
        #pragma unroll
        for (int r = 0; r < 4; r++)
            #pragma unroll
            for (int cp = 0; cp < 4; cp++)
                acc[r][cp] = (half == 0) ? pack2(b[c0 + 2*cp], b[c0 + 2*cp + 1]) : 0ULL;
        #pragma unroll 8
        for (int k = 0; k < 64; ++k) {
            float4 av = *(const float4*)&sA[k * 36 + r0];
            ulonglong2 w0 = *(const ulonglong2*)&sW[k * 128 + c0];
            ulonglong2 w1 = *(const ulonglong2*)&sW[k * 128 + c0 + 4];
            u64 ad[4] = {dup2(av.x), dup2(av.y), dup2(av.z), dup2(av.w)};
            u64 wp[4] = {w0.x, w0.y, w1.x, w1.y};
            #pragma unroll
            for (int r = 0; r < 4; r++)
                #pragma unroll
                for (int cp = 0; cp < 4; cp++)
                    acc[r][cp] = ffma2(ad[r], wp[cp], acc[r][cp]);
        }
        float* dst = (half == 0) ? g_S : g_P;
        #pragma unroll
        for (int r = 0; r < 4; r++) {
            int n = n0 + r0 + r;
            ulonglong2 q0, q1;
            q0.x = acc[r][0]; q0.y = acc[r][1];
            q1.x = acc[r][2]; q1.y = acc[r][3];
            *(ulonglong2*)&dst[n * C_DIM + c0]     = q0;
            *(ulonglong2*)&dst[n * C_DIM + c0 + 4] = q1;
        }
    }
}

// ---------------- K2: HMMA GEMM + gather epilogue + fused BN1 stats (R10) --
__global__ __launch_bounds__(128, 2) void k2_hmma(
        const float* __restrict__ nbr, const int* __restrict__ idx) {
    extern __shared__ __align__(1024) unsigned char SB[];
    const uint32_t sbase = smem_u32(SB);
    const int tid = threadIdx.x, wid = tid >> 5, lane = tid & 31;

    for (int i = tid; i < 128 * 8; i += 128) {
        int c = i >> 3, u = i & 7;
        uint32_t sw = SWZ((uint32_t)(c * 128 + u * 16));
        *(uint4*)(SB + SM_B_HI + sw) = *(const uint4*)&g_Wh[c * 64 + u * 8];
        *(uint4*)(SB + SM_B_LO + sw) = *(const uint4*)&g_Wl[c * 64 + u * 8];
    }
    __syncthreads();

    const int g    = lane >> 2, cq = lane & 3;
    const int sel  = lane >> 3;
    const int rsel = ((sel & 1) << 3) | (lane & 7);
    const int ksel = (sel >> 1) << 4;
    const int nsel = ((sel >> 1) << 3) | (lane & 7);
    const int kselB = (sel & 1) << 4;
    unsigned char* aHi = SB + SM_A_HI + (wid << 12);
    const uint32_t aBaseHi = sbase + SM_A_HI + (wid << 12);
    const uint32_t eBase   = sbase + SM_E    + (wid << 13);

    float lsum[2][16], lsq[2][16];
    #pragma unroll
    for (int h = 0; h < 2; ++h)
        #pragma unroll
        for (int i = 0; i < 16; ++i) { lsum[h][i] = 0.f; lsq[h][i] = 0.f; }

    for (int wt = blockIdx.x * 4 + wid; wt < NWTILES; wt += gridDim.x * 4) {
        const int p0 = wt * 32;

        #pragma unroll
        for (int pass = 0; pass < 4; ++pass) {
            int r  = pass * 8 + g;
            int c0 = cq * 16;
            #pragma unroll
            for (int q = 0; q < 4; ++q) {
                float4 v = __ldcs((const float4*)&nbr[(size_t)(p0 + r) * 64 + c0 + q * 4]);
                __nv_bfloat162 h0, h1;
                h0.x = __float2bfloat16(v.x); h0.y = __float2bfloat16(v.y);
                h1.x = __float2bfloat16(v.z); h1.y = __float2bfloat16(v.w);
                uint32_t sw = SWZ((uint32_t)(r * 128 + (c0 + q * 4) * 2));
                uint2 sh;
                sh.x = *(uint32_t*)&h0; sh.y = *(uint32_t*)&h1;
                *(uint2*)(aHi + sw) = sh;
            }
        }
        __syncwarp();

        uint32_t Af[4][2][4];
        #pragma unroll
        for (int ks = 0; ks < 4; ++ks)
            #pragma unroll
            for (int mf = 0; mf < 2; ++mf) {
                uint32_t byteA = (uint32_t)((mf * 16 + rsel) * 128 + ks * 32 + ksel);
                ldsm4(Af[ks][mf], aBaseHi + SWZ(byteA));
            }

        #pragma unroll
        for (int h = 0; h < 2; ++h) {
            float acc[2][8][4];
            #pragma unroll
            for (int mf = 0; mf < 2; ++mf)
                #pragma unroll
                for (int nf = 0; nf < 8; ++nf)
                    #pragma unroll
                    for (int e = 0; e < 4; ++e) acc[mf][nf][e] = 0.f;

            #pragma unroll
            for (int ks = 0; ks < 4; ++ks) {
                #pragma unroll
                for (int q = 0; q < 4; ++q) {
                    uint32_t byteB = (uint32_t)((h * 64 + q * 16 + nsel) * 128 + ks * 32 + kselB);
                    uint32_t Bh[4], Bl[4];
                    ldsm4(Bh, sbase + SM_B_HI + SWZ(byteB));
                    ldsm4(Bl, sbase + SM_B_LO + SWZ(byteB));
                    #pragma unroll
                    for (int mf = 0; mf < 2; ++mf) {
                        mma_bf16(acc[mf][q*2],   Af[ks][mf], Bh);
                        mma_bf16(acc[mf][q*2],   Af[ks][mf], Bl);
                        mma_bf16(acc[mf][q*2+1], Af[ks][mf], Bh + 2);
                        mma_bf16(acc[mf][q*2+1], Af[ks][mf], Bl + 2);
                    }
                }
            }

            #pragma unroll
            for (int mf = 0; mf < 2; ++mf)
                #pragma unroll
                for (int nf = 0; nf < 8; ++nf)
                    #pragma unroll
                    for (int rr = 0; rr < 2; ++rr) {
                        int r = mf * 16 + rr * 8 + g;
                        int c = nf * 8 + cq * 2;
                        uint32_t unit = ((uint32_t)r << 4) + ((uint32_t)(c >> 2) ^ (uint32_t)(r & 15));
                        uint32_t addr = eBase + (unit << 4) + ((uint32_t)(c & 3) << 2);
                        asm volatile("st.shared.v2.f32 [%0], {%1, %2};" ::
                            "r"(addr), "f"(acc[mf][nf][rr*2]), "f"(acc[mf][nf][rr*2+1]));
                    }
            __syncwarp();

            #pragma unroll
            for (int pass = 0; pass < 4; ++pass) {
                int r = pass * 8 + g;
                int p = p0 + r;
                int n = p / 12;
                int j = __ldg(&idx[p]);
                int cpart = cq * 16;
                float z[16];
                #pragma unroll
                for (int u = 0; u < 4; ++u) {
                    uint32_t unit = ((uint32_t)r << 4) +
                                    ((uint32_t)((cpart >> 2) + u) ^ (uint32_t)(r & 15));
                    float ex, ey, ez, ew;
                    asm volatile("ld.shared.v4.f32 {%0,%1,%2,%3}, [%4];"
                        : "=f"(ex), "=f"(ey), "=f"(ez), "=f"(ew) : "r"(eBase + (unit << 4)));
                    float4 s  = *(const float4*)&g_S[(size_t)n * C_DIM + h * 64 + cpart + u * 4];
                    float4 pv = *(const float4*)&g_P[(size_t)j * C_DIM + h * 64 + cpart + u * 4];
                    z[u*4+0] = ex + s.x + pv.x;
                    z[u*4+1] = ey + s.y + pv.y;
                    z[u*4+2] = ez + s.z + pv.z;
                    z[u*4+3] = ew + s.w + pv.w;
                }
                #pragma unroll
                for (int e = 0; e < 16; ++e) {
                    lsum[h][e] += z[e];
                    lsq[h][e]  = fmaf(z[e], z[e], lsq[h][e]);
                }
                uint4 st0, st1;
                {
                    __half2 a0 = __floats2half2_rn(z[0],  z[1]);
                    __half2 a1 = __floats2half2_rn(z[2],  z[3]);
                    __half2 a2 = __floats2half2_rn(z[4],  z[5]);
                    __half2 a3 = __floats2half2_rn(z[6],  z[7]);
                    __half2 a4 = __floats2half2_rn(z[8],  z[9]);
                    __half2 a5 = __floats2half2_rn(z[10], z[11]);
                    __half2 a6 = __floats2half2_rn(z[12], z[13]);
                    __half2 a7 = __floats2half2_rn(z[14], z[15]);
                    st0.x = *(uint32_t*)&a0; st0.y = *(uint32_t*)&a1;
                    st0.z = *(uint32_t*)&a2; st0.w = *(uint32_t*)&a3;
                    st1.x = *(uint32_t*)&a4; st1.y = *(uint32_t*)&a5;
                    st1.z = *(uint32_t*)&a6; st1.w = *(uint32_t*)&a7;
                }
                __stcs((uint4*)&g_Zh[(size_t)p * C_DIM + h * 64 + cpart],     st0);
                __stcs((uint4*)&g_Zh[(size_t)p * C_DIM + h * 64 + cpart + 8], st1);
            }
            __syncwarp();
        }
    }

    __syncthreads();
    float* st = (float*)SB;
    for (int i = tid; i < 512; i += 128) st[i] = 0.f;
    __syncthreads();
    #pragma unroll
    for (int h = 0; h < 2; ++h)
        #pragma unroll
        for (int e = 0; e < 16; ++e) {
            int ch = h * 64 + cq * 16 + e;
            atomicAdd(&st[ch],       lsum[h][e]);
            atomicAdd(&st[256 + ch], lsq[h][e]);
        }
    __syncthreads();
    if (tid < 128) {
        atomicAdd(&g_stats1[tid],       st[tid]);
        atomicAdd(&g_stats1[128 + tid], st[256 + tid]);
    }
}

// ---------------- K3 ----------------
__global__ void k3_aff1(const float* __restrict__ gamma1,
                        const float* __restrict__ beta1) {
    int c = threadIdx.x;
    float inv  = 1.f / (float)P_ROWS;
    float mean = g_stats1[c] * inv;
    float var  = g_stats1[128 + c] * inv - mean * mean;
    float sc   = gamma1[c] * rsqrtf(var + BN_EPS);
    g_aff1[c]       = sc;
    g_aff1[128 + c] = beta1[c] - mean * sc;
}

// ---------------- K4: 4-channel threads, uint2 streaming loads -------------
__global__ __launch_bounds__(256) void k4_reduce(const float* __restrict__ bw) {
    __shared__ float sSum[64], sSq[64];
    const int tid = threadIdx.x;
    if (tid < 64) { sSum[tid] = 0.f; sSq[tid] = 0.f; }
    __syncthreads();
    const int qd = tid & 15;        // channel quad: ch 4*qd .. 4*qd+3
    const int al = tid >> 4;        // 16 atom lanes
    const int c4 = qd * 4;
    float sc1[4], sh1[4], sc2[4], sh2[4];
    #pragma unroll
    for (int e = 0; e < 4; ++e) {
        sc1[e] = g_aff1[c4 + e];       sh1[e] = g_aff1[128 + c4 + e];
        sc2[e] = g_aff1[64 + c4 + e];  sh2[e] = g_aff1[192 + c4 + e];
    }
    float lsum[4] = {0.f, 0.f, 0.f, 0.f}, lsq[4] = {0.f, 0.f, 0.f, 0.f};

    for (int n = blockIdx.x * 16 + al; n < N_ATOMS; n += gridDim.x * 16) {
        float acc[4] = {0.f, 0.f, 0.f, 0.f};
        #pragma unroll
        for (int m = 0; m < 12; m++) {
            size_t base = (size_t)(n * 12 + m) * C_DIM;
            uint2 hf = __ldcs((const uint2*)&g_Zh[base + c4]);
            uint2 hc = __ldcs((const uint2*)&g_Zh[base + 64 + c4]);
            float2 f0 = __half22float2(*(__half2*)&hf.x);
            float2 f1 = __half22float2(*(__half2*)&hf.y);
            float2 c0 = __half22float2(*(__half2*)&hc.x);
            float2 c1 = __half22float2(*(__half2*)&hc.y);
            float w  = __ldg(&bw[n * 12 + m]);
            float w2 = w * w;
            float z1[4] = { fmaf(f0.x, sc1[0], sh1[0]), fmaf(f0.y, sc1[1], sh1[1]),
                            fmaf(f1.x, sc1[2], sh1[2]), fmaf(f1.y, sc1[3], sh1[3]) };
            float z2[4] = { fmaf(c0.x, sc2[0], sh2[0]), fmaf(c0.y, sc2[1], sh2[1]),
                            fmaf(c1.x, sc2[2], sh2[2]), fmaf(c1.y, sc2[3], sh2[3]) };
            #pragma unroll
            for (int e = 0; e < 4; ++e)
                acc[e] = fmaf(w2 * sigmoid_fast(z1[e]), softplus_fast(z2[e]), acc[e]);
        }
        float4 o; o.x = acc[0]; o.y = acc[1]; o.z = acc[2]; o.w = acc[3];
        *(float4*)&g_NS[n * 64 + c4] = o;
        #pragma unroll
        for (int e = 0; e < 4; ++e) {
            lsum[e] += acc[e];
            lsq[e]  = fmaf(acc[e], acc[e], lsq[e]);
        }
    }
    #pragma unroll
    for (int e = 0; e < 4; ++e) {
        atomicAdd(&sSum[c4 + e], lsum[e]);
        atomicAdd(&sSq[c4 + e],  lsq[e]);
    }
    __syncthreads();
    if (tid < 64) {
        atomicAdd(&g_stats2[tid],      sSum[tid]);
        atomicAdd(&g_stats2[64 + tid], sSq[tid]);
    }
}

// ---------------- K5 ----------------
__global__ void k5_aff2(const float* __restrict__ gamma2,
                        const float* __restrict__ beta2) {
    int f = threadIdx.x;
    float inv  = 1.f / (float)N_ATOMS;
    float mean = g_stats2[f] * inv;
    float var  = g_stats2[64 + f] * inv - mean * mean;
    float sc   = gamma2[f] * rsqrtf(var + BN_EPS);
    g_aff2[f]      = sc;
    g_aff2[64 + f] = beta2[f] - mean * sc;
}

// ---------------- K6 ----------------
__global__ void k6_out(const float* __restrict__ atom, float* __restrict__ out) {
    int i = blockIdx.x * blockDim.x + threadIdx.x;
    if (i < N_ATOMS * F_DIM) {
        int f = i & 63;
        float x = atom[i] + fmaf(g_NS[i], g_aff2[f], g_aff2[64 + f]);
        out[i] = softplus_fast(x);
    }
}

// ---------------- launch ----------------
extern "C" void kernel_launch(void* const* d_in, const int* in_sizes, int n_in,
                              void* d_out, int out_size) {
    const float* atom   = (const float*)d_in[0];
    const float* nbr    = (const float*)d_in[1];
    const float* bw     = (const float*)d_in[2];
    const int*   idx    = (const int*)  d_in[3];
    const float* W      = (const float*)d_in[4];
    const float* b      = (const float*)d_in[5];
    const float* gamma1 = (const float*)d_in[6];
    const float* beta1  = (const float*)d_in[7];
    const float* gamma2 = (const float*)d_in[8];
    const float* beta2  = (const float*)d_in[9];
    float* out = (float*)d_out;

    cudaFuncSetAttribute(k2_hmma, cudaFuncAttributeMaxDynamicSharedMemorySize, SM_TOT);

    k1_selfnbr<<<N_ATOMS / 32, 128>>>(atom, W, b);
    k2_hmma<<<296, 128, SM_TOT>>>(nbr, idx);
    k3_aff1<<<1, 128>>>(gamma1, beta1);
    k4_reduce<<<592, 256>>>(bw);
    k5_aff2<<<1, 64>>>(gamma2, beta2);
    k6_out<<<(N_ATOMS * F_DIM + 255) / 256, 256>>>(atom, out);
}

// round 14
// speedup vs baseline: 1.2241x; 1.0902x over previous
#include <cuda_runtime.h>
#include <cuda_fp16.h>
#include <cuda_bf16.h>
#include <stdint.h>
#include <math.h>

#define N_ATOMS 100000
#define M_NBR   12
#define F_DIM   64
#define C_DIM   128
#define KW      192
#define P_ROWS  (N_ATOMS * M_NBR)  // 1200000
#define BN_EPS  1e-5f
#define NWTILES (P_ROWS / 32)      // 37500 warp-tiles of 32 rows

typedef unsigned long long u64;

// ---------------- scratch ----------------
__device__ __align__(256) float  g_S [N_ATOMS * C_DIM];
__device__ __align__(256) float  g_P [N_ATOMS * C_DIM];
__device__ __align__(256) __half g_Zh[(size_t)P_ROWS * C_DIM];
__device__ __align__(256) float  g_NS[N_ATOMS * F_DIM];
__device__ __align__(256) __nv_bfloat16 g_Wh[C_DIM * 64];
__device__ __align__(256) __nv_bfloat16 g_Wl[C_DIM * 64];
__device__ float g_stats1[2 * C_DIM];
__device__ float g_stats2[2 * F_DIM];
__device__ float g_aff1 [2 * C_DIM];
__device__ float g_aff2 [2 * F_DIM];

// ---------------- helpers ----------------
__device__ __forceinline__ u64 pack2(float lo, float hi) {
    u64 r; asm("mov.b64 %0, {%1, %2};" : "=l"(r) : "r"(__float_as_uint(lo)), "r"(__float_as_uint(hi))); return r;
}
__device__ __forceinline__ u64 dup2(float a) {
    u64 r; unsigned int u = __float_as_uint(a);
    asm("mov.b64 %0, {%1, %1};" : "=l"(r) : "r"(u)); return r;
}
__device__ __forceinline__ u64 ffma2(u64 a, u64 b, u64 c) {
    u64 d; asm("fma.rn.f32x2 %0, %1, %2, %3;" : "=l"(d) : "l"(a), "l"(b), "l"(c)); return d;
}
__device__ __forceinline__ float tanh_fast(float x) {
    float y; asm("tanh.approx.f32 %0, %1;" : "=f"(y) : "f"(x)); return y;
}
__device__ __forceinline__ float sigmoid_fast(float x) {
    return fmaf(0.5f, tanh_fast(0.5f * x), 0.5f);
}
__device__ __forceinline__ float softplus_fast(float x) {
    return fmaxf(x, 0.f) + __logf(1.f + __expf(-fabsf(x)));
}
__device__ __forceinline__ uint32_t smem_u32(const void* p) {
    uint32_t a;
    asm("{ .reg .u64 t; cvta.to.shared.u64 t, %1; cvt.u32.u64 %0, t; }" : "=r"(a) : "l"(p));
    return a;
}
#define SWZ(b) ((b) ^ (((b) >> 3) & 0x70))

__device__ __forceinline__ void ldsm4(uint32_t* r, uint32_t addr) {
    asm volatile("ldmatrix.sync.aligned.m8n8.x4.shared.b16 {%0,%1,%2,%3}, [%4];"
        : "=r"(r[0]), "=r"(r[1]), "=r"(r[2]), "=r"(r[3]) : "r"(addr));
}
__device__ __forceinline__ void mma_bf16(float* d, const uint32_t* a, const uint32_t* b) {
    asm volatile("mma.sync.aligned.m16n8k16.row.col.f32.bf16.bf16.f32 "
        "{%0,%1,%2,%3}, {%4,%5,%6,%7}, {%8,%9}, {%0,%1,%2,%3};"
        : "+f"(d[0]), "+f"(d[1]), "+f"(d[2]), "+f"(d[3])
        : "r"(a[0]), "r"(a[1]), "r"(a[2]), "r"(a[3]), "r"(b[0]), "r"(b[1]));
}

// k2 smem layout (dynamic, 64KB)
#define SM_B_HI 0
#define SM_B_LO 16384
#define SM_A_HI 32768          // + wid*4096
#define SM_E    49152          // + wid*4096  (32 rows x 64 ch fp16, XOR swizzle)
#define SM_TOT  65536

// ---------------- K1: zero stats + W split (block 0) + S,P precompute -----
__global__ __launch_bounds__(128, 4) void k1_selfnbr(
        const float* __restrict__ atom, const float* __restrict__ W,
        const float* __restrict__ b) {
    __shared__ __align__(16) float sW[64 * 128];
    __shared__ __align__(16) float sA[64 * 36];
    const int tid = threadIdx.x;
    const int n0  = blockIdx.x * 32;

    if (blockIdx.x == 0) {
        if (tid < 128) { g_stats1[tid] = 0.f; g_stats1[128 + tid] = 0.f; }
        if (tid < 64)  { g_stats2[tid] = 0.f; g_stats2[64  + tid] = 0.f; }
        for (int i = tid; i < C_DIM * 64; i += 128) {
            int c = i >> 6, k = i & 63;
            float x = W[c * KW + 128 + k];
            __nv_bfloat16 hi = __float2bfloat16(x);
            __nv_bfloat16 lo = __float2bfloat16(x - __bfloat162float(hi));
            g_Wh[i] = hi; g_Wl[i] = lo;
        }
    }

    for (int i = tid; i < 32 * 64; i += 128) {
        int r = i >> 6, k = i & 63;
        sA[k * 36 + r] = atom[(n0 + r) * 64 + k];
    }
    const int rg = tid >> 4, cg = tid & 15;
    const int r0 = rg * 4,  c0 = cg * 8;
    for (int half = 0; half < 2; ++half) {
        __syncthreads();
        for (int i = tid; i < 64 * 128; i += 128) {
            int c = i >> 6, k = i & 63;
            sW[k * 128 + c] = W[c * KW + half * 64 + k];
        }
        __syncthreads();
        u64 acc[4][4];
        #pragma unroll
        for (int r = 0; r < 4; r++)
            #pragma unroll
            for (int cp = 0; cp < 4; cp++)
                acc[r][cp] = (half == 0) ? pack2(b[c0 + 2*cp], b[c0 + 2*cp + 1]) : 0ULL;
        #pragma unroll 8
        for (int k = 0; k < 64; ++k) {
            float4 av = *(const float4*)&sA[k * 36 + r0];
            ulonglong2 w0 = *(const ulonglong2*)&sW[k * 128 + c0];
            ulonglong2 w1 = *(const ulonglong2*)&sW[k * 128 + c0 + 4];
            u64 ad[4] = {dup2(av.x), dup2(av.y), dup2(av.z), dup2(av.w)};
            u64 wp[4] = {w0.x, w0.y, w1.x, w1.y};
            #pragma unroll
            for (int r = 0; r < 4; r++)
                #pragma unroll
                for (int cp = 0; cp < 4; cp++)
                    acc[r][cp] = ffma2(ad[r], wp[cp], acc[r][cp]);
        }
        float* dst = (half == 0) ? g_S : g_P;
        #pragma unroll
        for (int r = 0; r < 4; r++) {
            int n = n0 + r0 + r;
            ulonglong2 q0, q1;
            q0.x = acc[r][0]; q0.y = acc[r][1];
            q1.x = acc[r][2]; q1.y = acc[r][3];
            *(ulonglong2*)&dst[n * C_DIM + c0]     = q0;
            *(ulonglong2*)&dst[n * C_DIM + c0 + 4] = q1;
        }
    }
}

__global__ void knop() {}

// ---------------- K2: HMMA GEMM + fp16 E-stage + gather + fused BN1 stats --
__global__ __launch_bounds__(128, 3) void k2_hmma(
        const float* __restrict__ nbr, const int* __restrict__ idx) {
    extern __shared__ __align__(1024) unsigned char SB[];
    const uint32_t sbase = smem_u32(SB);
    const int tid = threadIdx.x, wid = tid >> 5, lane = tid & 31;

    for (int i = tid; i < 128 * 8; i += 128) {
        int c = i >> 3, u = i & 7;
        uint32_t sw = SWZ((uint32_t)(c * 128 + u * 16));
        *(uint4*)(SB + SM_B_HI + sw) = *(const uint4*)&g_Wh[c * 64 + u * 8];
        *(uint4*)(SB + SM_B_LO + sw) = *(const uint4*)&g_Wl[c * 64 + u * 8];
    }
    __syncthreads();

    const int g    = lane >> 2, cq = lane & 3;
    const int sel  = lane >> 3;
    const int rsel = ((sel & 1) << 3) | (lane & 7);
    const int ksel = (sel >> 1) << 4;
    const int nsel = ((sel >> 1) << 3) | (lane & 7);
    const int kselB = (sel & 1) << 4;
    unsigned char* aHi = SB + SM_A_HI + (wid << 12);
    const uint32_t aBaseHi = sbase + SM_A_HI + (wid << 12);
    const uint32_t eBase   = sbase + SM_E    + (wid << 12);

    float lsum[2][16], lsq[2][16];
    #pragma unroll
    for (int h = 0; h < 2; ++h)
        #pragma unroll
        for (int i = 0; i < 16; ++i) { lsum[h][i] = 0.f; lsq[h][i] = 0.f; }

    for (int wt = blockIdx.x * 4 + wid; wt < NWTILES; wt += gridDim.x * 4) {
        const int p0 = wt * 32;

        // stage A (32 rows x 64 f32 -> bf16 hi, SW128)
        #pragma unroll
        for (int pass = 0; pass < 4; ++pass) {
            int r  = pass * 8 + g;
            int c0 = cq * 16;
            #pragma unroll
            for (int q = 0; q < 4; ++q) {
                float4 v = __ldcs((const float4*)&nbr[(size_t)(p0 + r) * 64 + c0 + q * 4]);
                __nv_bfloat162 h0, h1;
                h0.x = __float2bfloat16(v.x); h0.y = __float2bfloat16(v.y);
                h1.x = __float2bfloat16(v.z); h1.y = __float2bfloat16(v.w);
                uint32_t sw = SWZ((uint32_t)(r * 128 + (c0 + q * 4) * 2));
                uint2 sh;
                sh.x = *(uint32_t*)&h0; sh.y = *(uint32_t*)&h1;
                *(uint2*)(aHi + sw) = sh;
            }
        }
        __syncwarp();

        uint32_t Af[4][2][4];
        #pragma unroll
        for (int ks = 0; ks < 4; ++ks)
            #pragma unroll
            for (int mf = 0; mf < 2; ++mf) {
                uint32_t byteA = (uint32_t)((mf * 16 + rsel) * 128 + ks * 32 + ksel);
                ldsm4(Af[ks][mf], aBaseHi + SWZ(byteA));
            }

        #pragma unroll
        for (int h = 0; h < 2; ++h) {
            float acc[2][8][4];
            #pragma unroll
            for (int mf = 0; mf < 2; ++mf)
                #pragma unroll
                for (int nf = 0; nf < 8; ++nf)
                    #pragma unroll
                    for (int e = 0; e < 4; ++e) acc[mf][nf][e] = 0.f;

            #pragma unroll
            for (int ks = 0; ks < 4; ++ks) {
                #pragma unroll
                for (int q = 0; q < 4; ++q) {
                    uint32_t byteB = (uint32_t)((h * 64 + q * 16 + nsel) * 128 + ks * 32 + kselB);
                    uint32_t Bh[4], Bl[4];
                    ldsm4(Bh, sbase + SM_B_HI + SWZ(byteB));
                    ldsm4(Bl, sbase + SM_B_LO + SWZ(byteB));
                    #pragma unroll
                    for (int mf = 0; mf < 2; ++mf) {
                        mma_bf16(acc[mf][q*2],   Af[ks][mf], Bh);
                        mma_bf16(acc[mf][q*2],   Af[ks][mf], Bl);
                        mma_bf16(acc[mf][q*2+1], Af[ks][mf], Bh + 2);
                        mma_bf16(acc[mf][q*2+1], Af[ks][mf], Bl + 2);
                    }
                }
            }

            // stage acc -> E fp16 (32 rows x 64 ch, XOR swizzle on 16B units)
            #pragma unroll
            for (int mf = 0; mf < 2; ++mf)
                #pragma unroll
                for (int nf = 0; nf < 8; ++nf)
                    #pragma unroll
                    for (int rr = 0; rr < 2; ++rr) {
                        int r = mf * 16 + rr * 8 + g;
                        int c = nf * 8 + cq * 2;                 // even channel
                        __half2 hv = __floats2half2_rn(acc[mf][nf][rr*2], acc[mf][nf][rr*2+1]);
                        uint32_t byte = ((uint32_t)c * 2) ^ (((uint32_t)r & 7) << 4);
                        uint32_t addr = eBase + (uint32_t)r * 128 + byte;
                        asm volatile("st.shared.b32 [%0], %1;" ::
                            "r"(addr), "r"(*(uint32_t*)&hv));
                    }
            __syncwarp();

            // epilogue: row r, 16 channels; read E fp16, add S+P, stats, Z store
            #pragma unroll
            for (int pass = 0; pass < 4; ++pass) {
                int r = pass * 8 + g;
                int p = p0 + r;
                int n = p / 12;
                int j = __ldg(&idx[p]);
                int cpart = cq * 16;
                float z[16];
                #pragma unroll
                for (int half16 = 0; half16 < 2; ++half16) {
                    uint32_t byte = (((uint32_t)(cpart + half16 * 8) * 2)) ^ (((uint32_t)r & 7) << 4);
                    uint32_t a0, a1, a2, a3;
                    asm volatile("ld.shared.v4.b32 {%0,%1,%2,%3}, [%4];"
                        : "=r"(a0), "=r"(a1), "=r"(a2), "=r"(a3)
                        : "r"(eBase + (uint32_t)r * 128 + byte));
                    float2 e0 = __half22float2(*(__half2*)&a0);
                    float2 e1 = __half22float2(*(__half2*)&a1);
                    float2 e2 = __half22float2(*(__half2*)&a2);
                    float2 e3 = __half22float2(*(__half2*)&a3);
                    float4 s0 = *(const float4*)&g_S[(size_t)n * C_DIM + h * 64 + cpart + half16 * 8];
                    float4 s1 = *(const float4*)&g_S[(size_t)n * C_DIM + h * 64 + cpart + half16 * 8 + 4];
                    float4 p0v = *(const float4*)&g_P[(size_t)j * C_DIM + h * 64 + cpart + half16 * 8];
                    float4 p1v = *(const float4*)&g_P[(size_t)j * C_DIM + h * 64 + cpart + half16 * 8 + 4];
                    int o = half16 * 8;
                    z[o+0] = e0.x + s0.x + p0v.x;  z[o+1] = e0.y + s0.y + p0v.y;
                    z[o+2] = e1.x + s0.z + p0v.z;  z[o+3] = e1.y + s0.w + p0v.w;
                    z[o+4] = e2.x + s1.x + p1v.x;  z[o+5] = e2.y + s1.y + p1v.y;
                    z[o+6] = e3.x + s1.z + p1v.z;  z[o+7] = e3.y + s1.w + p1v.w;
                }
                #pragma unroll
                for (int e = 0; e < 16; ++e) {
                    lsum[h][e] += z[e];
                    lsq[h][e]  = fmaf(z[e], z[e], lsq[h][e]);
                }
                uint4 st0, st1;
                {
                    __half2 a0 = __floats2half2_rn(z[0],  z[1]);
                    __half2 a1 = __floats2half2_rn(z[2],  z[3]);
                    __half2 a2 = __floats2half2_rn(z[4],  z[5]);
                    __half2 a3 = __floats2half2_rn(z[6],  z[7]);
                    __half2 a4 = __floats2half2_rn(z[8],  z[9]);
                    __half2 a5 = __floats2half2_rn(z[10], z[11]);
                    __half2 a6 = __floats2half2_rn(z[12], z[13]);
                    __half2 a7 = __floats2half2_rn(z[14], z[15]);
                    st0.x = *(uint32_t*)&a0; st0.y = *(uint32_t*)&a1;
                    st0.z = *(uint32_t*)&a2; st0.w = *(uint32_t*)&a3;
                    st1.x = *(uint32_t*)&a4; st1.y = *(uint32_t*)&a5;
                    st1.z = *(uint32_t*)&a6; st1.w = *(uint32_t*)&a7;
                }
                __stcs((uint4*)&g_Zh[(size_t)p * C_DIM + h * 64 + cpart],     st0);
                __stcs((uint4*)&g_Zh[(size_t)p * C_DIM + h * 64 + cpart + 8], st1);
            }
            __syncwarp();
        }
    }

    __syncthreads();
    float* st = (float*)SB;
    for (int i = tid; i < 512; i += 128) st[i] = 0.f;
    __syncthreads();
    #pragma unroll
    for (int h = 0; h < 2; ++h)
        #pragma unroll
        for (int e = 0; e < 16; ++e) {
            int ch = h * 64 + cq * 16 + e;
            atomicAdd(&st[ch],       lsum[h][e]);
            atomicAdd(&st[256 + ch], lsq[h][e]);
        }
    __syncthreads();
    if (tid < 128) {
        atomicAdd(&g_stats1[tid],       st[tid]);
        atomicAdd(&g_stats1[128 + tid], st[256 + tid]);
    }
}

// ---------------- K3 ----------------
__global__ void k3_aff1(const float* __restrict__ gamma1,
                        const float* __restrict__ beta1) {
    int c = threadIdx.x;
    float inv  = 1.f / (float)P_ROWS;
    float mean = g_stats1[c] * inv;
    float var  = g_stats1[128 + c] * inv - mean * mean;
    float sc   = gamma1[c] * rsqrtf(var + BN_EPS);
    g_aff1[c]       = sc;
    g_aff1[128 + c] = beta1[c] - mean * sc;
}

// ---------------- K4 ----------------
__global__ __launch_bounds__(256) void k4_reduce(const float* __restrict__ bw) {
    __shared__ float sSum[64], sSq[64];
    const int tid = threadIdx.x;
    if (tid < 64) { sSum[tid] = 0.f; sSq[tid] = 0.f; }
    __syncthreads();
    const int qd = tid & 15;
    const int al = tid >> 4;
    const int c4 = qd * 4;
    float sc1[4], sh1[4], sc2[4], sh2[4];
    #pragma unroll
    for (int e = 0; e < 4; ++e) {
        sc1[e] = g_aff1[c4 + e];       sh1[e] = g_aff1[128 + c4 + e];
        sc2[e] = g_aff1[64 + c4 + e];  sh2[e] = g_aff1[192 + c4 + e];
    }
    float lsum[4] = {0.f, 0.f, 0.f, 0.f}, lsq[4] = {0.f, 0.f, 0.f, 0.f};

    for (int n = blockIdx.x * 16 + al; n < N_ATOMS; n += gridDim.x * 16) {
        float acc[4] = {0.f, 0.f, 0.f, 0.f};
        #pragma unroll
        for (int m = 0; m < 12; m++) {
            size_t base = (size_t)(n * 12 + m) * C_DIM;
            uint2 hf = __ldcs((const uint2*)&g_Zh[base + c4]);
            uint2 hc = __ldcs((const uint2*)&g_Zh[base + 64 + c4]);
            float2 f0 = __half22float2(*(__half2*)&hf.x);
            float2 f1 = __half22float2(*(__half2*)&hf.y);
            float2 c0 = __half22float2(*(__half2*)&hc.x);
            float2 c1 = __half22float2(*(__half2*)&hc.y);
            float w  = __ldg(&bw[n * 12 + m]);
            float w2 = w * w;
            float z1[4] = { fmaf(f0.x, sc1[0], sh1[0]), fmaf(f0.y, sc1[1], sh1[1]),
                            fmaf(f1.x, sc1[2], sh1[2]), fmaf(f1.y, sc1[3], sh1[3]) };
            float z2[4] = { fmaf(c0.x, sc2[0], sh2[0]), fmaf(c0.y, sc2[1], sh2[1]),
                            fmaf(c1.x, sc2[2], sh2[2]), fmaf(c1.y, sc2[3], sh2[3]) };
            #pragma unroll
            for (int e = 0; e < 4; ++e)
                acc[e] = fmaf(w2 * sigmoid_fast(z1[e]), softplus_fast(z2[e]), acc[e]);
        }
        float4 o; o.x = acc[0]; o.y = acc[1]; o.z = acc[2]; o.w = acc[3];
        *(float4*)&g_NS[n * 64 + c4] = o;
        #pragma unroll
        for (int e = 0; e < 4; ++e) {
            lsum[e] += acc[e];
            lsq[e]  = fmaf(acc[e], acc[e], lsq[e]);
        }
    }
    #pragma unroll
    for (int e = 0; e < 4; ++e) {
        atomicAdd(&sSum[c4 + e], lsum[e]);
        atomicAdd(&sSq[c4 + e],  lsq[e]);
    }
    __syncthreads();
    if (tid < 64) {
        atomicAdd(&g_stats2[tid],      sSum[tid]);
        atomicAdd(&g_stats2[64 + tid], sSq[tid]);
    }
}

// ---------------- K5 ----------------
__global__ void k5_aff2(const float* __restrict__ gamma2,
                        const float* __restrict__ beta2) {
    int f = threadIdx.x;
    float inv  = 1.f / (float)N_ATOMS;
    float mean = g_stats2[f] * inv;
    float var  = g_stats2[64 + f] * inv - mean * mean;
    float sc   = gamma2[f] * rsqrtf(var + BN_EPS);
    g_aff2[f]      = sc;
    g_aff2[64 + f] = beta2[f] - mean * sc;
}

// ---------------- K6 ----------------
__global__ void k6_out(const float* __restrict__ atom, float* __restrict__ out) {
    int i = blockIdx.x * blockDim.x + threadIdx.x;
    if (i < N_ATOMS * F_DIM) {
        int f = i & 63;
        float x = atom[i] + fmaf(g_NS[i], g_aff2[f], g_aff2[64 + f]);
        out[i] = softplus_fast(x);
    }
}

// ---------------- launch ----------------
extern "C" void kernel_launch(void* const* d_in, const int* in_sizes, int n_in,
                              void* d_out, int out_size) {
    const float* atom   = (const float*)d_in[0];
    const float* nbr    = (const float*)d_in[1];
    const float* bw     = (const float*)d_in[2];
    const int*   idx    = (const int*)  d_in[3];
    const float* W      = (const float*)d_in[4];
    const float* b      = (const float*)d_in[5];
    const float* gamma1 = (const float*)d_in[6];
    const float* beta1  = (const float*)d_in[7];
    const float* gamma2 = (const float*)d_in[8];
    const float* beta2  = (const float*)d_in[9];
    float* out = (float*)d_out;

    cudaFuncSetAttribute(k2_hmma, cudaFuncAttributeMaxDynamicSharedMemorySize, SM_TOT);

    k1_selfnbr<<<N_ATOMS / 32, 128>>>(atom, W, b);
    knop<<<1, 32>>>();
    knop<<<1, 32>>>();
    k2_hmma<<<444, 128, SM_TOT>>>(nbr, idx);
    k3_aff1<<<1, 128>>>(gamma1, beta1);
    k4_reduce<<<592, 256>>>(bw);
    k5_aff2<<<1, 64>>>(gamma2, beta2);
    k6_out<<<(N_ATOMS * F_DIM + 255) / 256, 256>>>(atom, out);
}

// round 15
// speedup vs baseline: 1.7633x; 1.4405x over previous
#include <cuda_runtime.h>
#include <cuda_fp16.h>
#include <cuda_bf16.h>
#include <stdint.h>
#include <math.h>

#define N_ATOMS 100000
#define M_NBR   12
#define F_DIM   64
#define C_DIM   128
#define KW      192
#define P_ROWS  (N_ATOMS * M_NBR)  // 1200000
#define BN_EPS  1e-5f
#define NWTILES (P_ROWS / 32)      // 37500
#define NATILES (N_ATOMS / 32)     // 3125

typedef unsigned long long u64;

// ---------------- scratch ----------------
__device__ __align__(256) float  g_S [N_ATOMS * C_DIM];
__device__ __align__(256) float  g_P [N_ATOMS * C_DIM];
__device__ __align__(256) __half g_Zh[(size_t)P_ROWS * C_DIM];
__device__ __align__(256) float  g_NS[N_ATOMS * F_DIM];
__device__ __align__(256) __nv_bfloat16 g_Wh[C_DIM * 64];
__device__ __align__(256) __nv_bfloat16 g_Wl[C_DIM * 64];
__device__ float g_stats1[2 * C_DIM];
__device__ float g_stats2[2 * F_DIM];
__device__ float g_aff1 [2 * C_DIM];
__device__ float g_aff2 [2 * F_DIM];

// ---------------- helpers ----------------
__device__ __forceinline__ float tanh_fast(float x) {
    float y; asm("tanh.approx.f32 %0, %1;" : "=f"(y) : "f"(x)); return y;
}
__device__ __forceinline__ float sigmoid_fast(float x) {
    return fmaf(0.5f, tanh_fast(0.5f * x), 0.5f);
}
__device__ __forceinline__ float softplus_fast(float x) {
    return fmaxf(x, 0.f) + __logf(1.f + __expf(-fabsf(x)));
}
__device__ __forceinline__ uint32_t smem_u32(const void* p) {
    uint32_t a;
    asm("{ .reg .u64 t; cvta.to.shared.u64 t, %1; cvt.u32.u64 %0, t; }" : "=r"(a) : "l"(p));
    return a;
}
#define SWZ(b) ((b) ^ (((b) >> 3) & 0x70))

__device__ __forceinline__ void ldsm4(uint32_t* r, uint32_t addr) {
    asm volatile("ldmatrix.sync.aligned.m8n8.x4.shared.b16 {%0,%1,%2,%3}, [%4];"
        : "=r"(r[0]), "=r"(r[1]), "=r"(r[2]), "=r"(r[3]) : "r"(addr));
}
__device__ __forceinline__ void mma_bf16(float* d, const uint32_t* a, const uint32_t* b) {
    asm volatile("mma.sync.aligned.m16n8k16.row.col.f32.bf16.bf16.f32 "
        "{%0,%1,%2,%3}, {%4,%5,%6,%7}, {%8,%9}, {%0,%1,%2,%3};"
        : "+f"(d[0]), "+f"(d[1]), "+f"(d[2]), "+f"(d[3])
        : "r"(a[0]), "r"(a[1]), "r"(a[2]), "r"(a[3]), "r"(b[0]), "r"(b[1]));
}
__device__ __forceinline__ void split_bf16x2(float x, float y,
                                             uint32_t& hi, uint32_t& lo) {
    __nv_bfloat162 h, l;
    h.x = __float2bfloat16(x); h.y = __float2bfloat16(y);
    l.x = __float2bfloat16(x - __bfloat162float(h.x));
    l.y = __float2bfloat16(y - __bfloat162float(h.y));
    hi = *(uint32_t*)&h; lo = *(uint32_t*)&l;
}

__global__ void knop() {}

// ============ K1: HMMA S,P precompute (full hi/lo split) ============
// smem: B_hi 256x128B (32KB) | B_lo (32KB) | per-warp A hi/lo (4KB+4KB)x4
#define K1_B_HI 0
#define K1_B_LO 32768
#define K1_A    65536
#define K1_TOT  98304

__global__ __launch_bounds__(128, 2) void k1_hmma(
        const float* __restrict__ atom, const float* __restrict__ W,
        const float* __restrict__ b) {
    extern __shared__ __align__(1024) unsigned char SB[];
    const uint32_t sbase = smem_u32(SB);
    const int tid = threadIdx.x, wid = tid >> 5, lane = tid & 31;

    if (blockIdx.x == 0) {
        if (tid < 128) { g_stats1[tid] = 0.f; g_stats1[128 + tid] = 0.f; }
        if (tid < 64)  { g_stats2[tid] = 0.f; g_stats2[64  + tid] = 0.f; }
        for (int i = tid; i < C_DIM * 64; i += 128) {
            int c = i >> 6, k = i & 63;
            float x = W[c * KW + 128 + k];
            __nv_bfloat16 hi = __float2bfloat16(x);
            __nv_bfloat16 lo = __float2bfloat16(x - __bfloat162float(hi));
            g_Wh[i] = hi; g_Wl[i] = lo;
        }
    }

    // stage W_self|W_nbr as 256 ch-rows x 64 k (hi/lo, SW128)
    for (int i = tid; i < 256 * 8; i += 128) {
        int c = i >> 3, u = i & 7;
        const float* src = (c < 128) ? &W[c * KW + u * 8]
                                     : &W[(c - 128) * KW + 64 + u * 8];
        float4 va = *(const float4*)src;
        float4 vb = *(const float4*)(src + 4);
        uint4 hi4, lo4;
        split_bf16x2(va.x, va.y, hi4.x, lo4.x);
        split_bf16x2(va.z, va.w, hi4.y, lo4.y);
        split_bf16x2(vb.x, vb.y, hi4.z, lo4.z);
        split_bf16x2(vb.z, vb.w, hi4.w, lo4.w);
        uint32_t sw = SWZ((uint32_t)(c * 128 + u * 16));
        *(uint4*)(SB + K1_B_HI + sw) = hi4;
        *(uint4*)(SB + K1_B_LO + sw) = lo4;
    }
    __syncthreads();

    const int g    = lane >> 2, cq = lane & 3;
    const int sel  = lane >> 3;
    const int rsel = ((sel & 1) << 3) | (lane & 7);
    const int ksel = (sel >> 1) << 4;
    const int nsel = ((sel >> 1) << 3) | (lane & 7);
    const int kselB = (sel & 1) << 4;
    unsigned char* aW = SB + K1_A + (wid << 13);
    const uint32_t aBase = sbase + K1_A + (wid << 13);

    for (int wt = blockIdx.x * 4 + wid; wt < NATILES; wt += gridDim.x * 4) {
        const int n0 = wt * 32;

        // stage atom tile hi/lo
        #pragma unroll
        for (int pass = 0; pass < 4; ++pass) {
            int r  = pass * 8 + g;
            int c0 = cq * 16;
            #pragma unroll
            for (int q = 0; q < 4; ++q) {
                float4 v = *(const float4*)&atom[(size_t)(n0 + r) * 64 + c0 + q * 4];
                uint2 sh, sl;
                split_bf16x2(v.x, v.y, sh.x, sl.x);
                split_bf16x2(v.z, v.w, sh.y, sl.y);
                uint32_t sw = SWZ((uint32_t)(r * 128 + (c0 + q * 4) * 2));
                *(uint2*)(aW + sw)        = sh;
                *(uint2*)(aW + 4096 + sw) = sl;
            }
        }
        __syncwarp();

        #pragma unroll
        for (int chunk = 0; chunk < 4; ++chunk) {
            float acc[2][8][4];
            #pragma unroll
            for (int mf = 0; mf < 2; ++mf)
                #pragma unroll
                for (int nf = 0; nf < 8; ++nf)
                    #pragma unroll
                    for (int e = 0; e < 4; ++e) acc[mf][nf][e] = 0.f;

            #pragma unroll
            for (int ks = 0; ks < 4; ++ks) {
                uint32_t Ah[2][4], Al[2][4];
                #pragma unroll
                for (int mf = 0; mf < 2; ++mf) {
                    uint32_t byteA = (uint32_t)((mf * 16 + rsel) * 128 + ks * 32 + ksel);
                    ldsm4(Ah[mf], aBase + SWZ(byteA));
                    ldsm4(Al[mf], aBase + 4096 + SWZ(byteA));
                }
                #pragma unroll
                for (int q = 0; q < 4; ++q) {
                    uint32_t byteB = (uint32_t)((chunk * 64 + q * 16 + nsel) * 128 + ks * 32 + kselB);
                    uint32_t Bh[4], Bl[4];
                    ldsm4(Bh, sbase + K1_B_HI + SWZ(byteB));
                    ldsm4(Bl, sbase + K1_B_LO + SWZ(byteB));
                    #pragma unroll
                    for (int mf = 0; mf < 2; ++mf) {
                        mma_bf16(acc[mf][q*2],   Ah[mf], Bh);
                        mma_bf16(acc[mf][q*2],   Ah[mf], Bl);
                        mma_bf16(acc[mf][q*2],   Al[mf], Bh);
                        mma_bf16(acc[mf][q*2+1], Ah[mf], Bh + 2);
                        mma_bf16(acc[mf][q*2+1], Ah[mf], Bl + 2);
                        mma_bf16(acc[mf][q*2+1], Al[mf], Bh + 2);
                    }
                }
            }

            // direct store: S for chunk<2 (+bias), P for chunk>=2
            float* dst = (chunk < 2) ? g_S : g_P;
            const int cbase = (chunk & 1) * 64;
            #pragma unroll
            for (int nf = 0; nf < 8; ++nf) {
                int c = cbase + nf * 8 + cq * 2;
                float b0 = 0.f, b1 = 0.f;
                if (chunk < 2) {
                    float2 bv = *(const float2*)&b[c];
                    b0 = bv.x; b1 = bv.y;
                }
                #pragma unroll
                for (int mf = 0; mf < 2; ++mf)
                    #pragma unroll
                    for (int rr = 0; rr < 2; ++rr) {
                        int n = n0 + mf * 16 + rr * 8 + g;
                        float2 o;
                        o.x = acc[mf][nf][rr*2]   + b0;
                        o.y = acc[mf][nf][rr*2+1] + b1;
                        *(float2*)&dst[(size_t)n * C_DIM + c] = o;
                    }
            }
        }
        __syncwarp();
    }
}

// k2 smem layout (dynamic, 64KB)
#define SM_B_HI 0
#define SM_B_LO 16384
#define SM_A_HI 32768
#define SM_E    49152
#define SM_TOT  65536

// ---------------- K2: HMMA GEMM + fp16 E-stage + gather + fused BN1 stats --
__global__ __launch_bounds__(128, 3) void k2_hmma(
        const float* __restrict__ nbr, const int* __restrict__ idx) {
    extern __shared__ __align__(1024) unsigned char SB[];
    const uint32_t sbase = smem_u32(SB);
    const int tid = threadIdx.x, wid = tid >> 5, lane = tid & 31;

    for (int i = tid; i < 128 * 8; i += 128) {
        int c = i >> 3, u = i & 7;
        uint32_t sw = SWZ((uint32_t)(c * 128 + u * 16));
        *(uint4*)(SB + SM_B_HI + sw) = *(const uint4*)&g_Wh[c * 64 + u * 8];
        *(uint4*)(SB + SM_B_LO + sw) = *(const uint4*)&g_Wl[c * 64 + u * 8];
    }
    __syncthreads();

    const int g    = lane >> 2, cq = lane & 3;
    const int sel  = lane >> 3;
    const int rsel = ((sel & 1) << 3) | (lane & 7);
    const int ksel = (sel >> 1) << 4;
    const int nsel = ((sel >> 1) << 3) | (lane & 7);
    const int kselB = (sel & 1) << 4;
    unsigned char* aHi = SB + SM_A_HI + (wid << 12);
    const uint32_t aBaseHi = sbase + SM_A_HI + (wid << 12);
    const uint32_t eBase   = sbase + SM_E    + (wid << 12);

    float lsum[2][16], lsq[2][16];
    #pragma unroll
    for (int h = 0; h < 2; ++h)
        #pragma unroll
        for (int i = 0; i < 16; ++i) { lsum[h][i] = 0.f; lsq[h][i] = 0.f; }

    for (int wt = blockIdx.x * 4 + wid; wt < NWTILES; wt += gridDim.x * 4) {
        const int p0 = wt * 32;

        #pragma unroll
        for (int pass = 0; pass < 4; ++pass) {
            int r  = pass * 8 + g;
            int c0 = cq * 16;
            #pragma unroll
            for (int q = 0; q < 4; ++q) {
                float4 v = __ldcs((const float4*)&nbr[(size_t)(p0 + r) * 64 + c0 + q * 4]);
                __nv_bfloat162 h0, h1;
                h0.x = __float2bfloat16(v.x); h0.y = __float2bfloat16(v.y);
                h1.x = __float2bfloat16(v.z); h1.y = __float2bfloat16(v.w);
                uint32_t sw = SWZ((uint32_t)(r * 128 + (c0 + q * 4) * 2));
                uint2 sh;
                sh.x = *(uint32_t*)&h0; sh.y = *(uint32_t*)&h1;
                *(uint2*)(aHi + sw) = sh;
            }
        }
        __syncwarp();

        uint32_t Af[4][2][4];
        #pragma unroll
        for (int ks = 0; ks < 4; ++ks)
            #pragma unroll
            for (int mf = 0; mf < 2; ++mf) {
                uint32_t byteA = (uint32_t)((mf * 16 + rsel) * 128 + ks * 32 + ksel);
                ldsm4(Af[ks][mf], aBaseHi + SWZ(byteA));
            }

        #pragma unroll
        for (int h = 0; h < 2; ++h) {
            float acc[2][8][4];
            #pragma unroll
            for (int mf = 0; mf < 2; ++mf)
                #pragma unroll
                for (int nf = 0; nf < 8; ++nf)
                    #pragma unroll
                    for (int e = 0; e < 4; ++e) acc[mf][nf][e] = 0.f;

            #pragma unroll
            for (int ks = 0; ks < 4; ++ks) {
                #pragma unroll
                for (int q = 0; q < 4; ++q) {
                    uint32_t byteB = (uint32_t)((h * 64 + q * 16 + nsel) * 128 + ks * 32 + kselB);
                    uint32_t Bh[4], Bl[4];
                    ldsm4(Bh, sbase + SM_B_HI + SWZ(byteB));
                    ldsm4(Bl, sbase + SM_B_LO + SWZ(byteB));
                    #pragma unroll
                    for (int mf = 0; mf < 2; ++mf) {
                        mma_bf16(acc[mf][q*2],   Af[ks][mf], Bh);
                        mma_bf16(acc[mf][q*2],   Af[ks][mf], Bl);
                        mma_bf16(acc[mf][q*2+1], Af[ks][mf], Bh + 2);
                        mma_bf16(acc[mf][q*2+1], Af[ks][mf], Bl + 2);
                    }
                }
            }

            #pragma unroll
            for (int mf = 0; mf < 2; ++mf)
                #pragma unroll
                for (int nf = 0; nf < 8; ++nf)
                    #pragma unroll
                    for (int rr = 0; rr < 2; ++rr) {
                        int r = mf * 16 + rr * 8 + g;
                        int c = nf * 8 + cq * 2;
                        __half2 hv = __floats2half2_rn(acc[mf][nf][rr*2], acc[mf][nf][rr*2+1]);
                        uint32_t byte = ((uint32_t)c * 2) ^ (((uint32_t)r & 7) << 4);
                        uint32_t addr = eBase + (uint32_t)r * 128 + byte;
                        asm volatile("st.shared.b32 [%0], %1;" ::
                            "r"(addr), "r"(*(uint32_t*)&hv));
                    }
            __syncwarp();

            #pragma unroll
            for (int pass = 0; pass < 4; ++pass) {
                int r = pass * 8 + g;
                int p = p0 + r;
                int n = p / 12;
                int j = __ldg(&idx[p]);
                int cpart = cq * 16;
                float z[16];
                #pragma unroll
                for (int half16 = 0; half16 < 2; ++half16) {
                    uint32_t byte = (((uint32_t)(cpart + half16 * 8) * 2)) ^ (((uint32_t)r & 7) << 4);
                    uint32_t a0, a1, a2, a3;
                    asm volatile("ld.shared.v4.b32 {%0,%1,%2,%3}, [%4];"
                        : "=r"(a0), "=r"(a1), "=r"(a2), "=r"(a3)
                        : "r"(eBase + (uint32_t)r * 128 + byte));
                    float2 e0 = __half22float2(*(__half2*)&a0);
                    float2 e1 = __half22float2(*(__half2*)&a1);
                    float2 e2 = __half22float2(*(__half2*)&a2);
                    float2 e3 = __half22float2(*(__half2*)&a3);
                    float4 s0 = *(const float4*)&g_S[(size_t)n * C_DIM + h * 64 + cpart + half16 * 8];
                    float4 s1 = *(const float4*)&g_S[(size_t)n * C_DIM + h * 64 + cpart + half16 * 8 + 4];
                    float4 p0v = *(const float4*)&g_P[(size_t)j * C_DIM + h * 64 + cpart + half16 * 8];
                    float4 p1v = *(const float4*)&g_P[(size_t)j * C_DIM + h * 64 + cpart + half16 * 8 + 4];
                    int o = half16 * 8;
                    z[o+0] = e0.x + s0.x + p0v.x;  z[o+1] = e0.y + s0.y + p0v.y;
                    z[o+2] = e1.x + s0.z + p0v.z;  z[o+3] = e1.y + s0.w + p0v.w;
                    z[o+4] = e2.x + s1.x + p1v.x;  z[o+5] = e2.y + s1.y + p1v.y;
                    z[o+6] = e3.x + s1.z + p1v.z;  z[o+7] = e3.y + s1.w + p1v.w;
                }
                #pragma unroll
                for (int e = 0; e < 16; ++e) {
                    lsum[h][e] += z[e];
                    lsq[h][e]  = fmaf(z[e], z[e], lsq[h][e]);
                }
                uint4 st0, st1;
                {
                    __half2 a0 = __floats2half2_rn(z[0],  z[1]);
                    __half2 a1 = __floats2half2_rn(z[2],  z[3]);
                    __half2 a2 = __floats2half2_rn(z[4],  z[5]);
                    __half2 a3 = __floats2half2_rn(z[6],  z[7]);
                    __half2 a4 = __floats2half2_rn(z[8],  z[9]);
                    __half2 a5 = __floats2half2_rn(z[10], z[11]);
                    __half2 a6 = __floats2half2_rn(z[12], z[13]);
                    __half2 a7 = __floats2half2_rn(z[14], z[15]);
                    st0.x = *(uint32_t*)&a0; st0.y = *(uint32_t*)&a1;
                    st0.z = *(uint32_t*)&a2; st0.w = *(uint32_t*)&a3;
                    st1.x = *(uint32_t*)&a4; st1.y = *(uint32_t*)&a5;
                    st1.z = *(uint32_t*)&a6; st1.w = *(uint32_t*)&a7;
                }
                __stcs((uint4*)&g_Zh[(size_t)p * C_DIM + h * 64 + cpart],     st0);
                __stcs((uint4*)&g_Zh[(size_t)p * C_DIM + h * 64 + cpart + 8], st1);
            }
            __syncwarp();
        }
    }

    __syncthreads();
    float* st = (float*)SB;
    for (int i = tid; i < 512; i += 128) st[i] = 0.f;
    __syncthreads();
    #pragma unroll
    for (int h = 0; h < 2; ++h)
        #pragma unroll
        for (int e = 0; e < 16; ++e) {
            int ch = h * 64 + cq * 16 + e;
            atomicAdd(&st[ch],       lsum[h][e]);
            atomicAdd(&st[256 + ch], lsq[h][e]);
        }
    __syncthreads();
    if (tid < 128) {
        atomicAdd(&g_stats1[tid],       st[tid]);
        atomicAdd(&g_stats1[128 + tid], st[256 + tid]);
    }
}

// ---------------- K3 ----------------
__global__ void k3_aff1(const float* __restrict__ gamma1,
                        const float* __restrict__ beta1) {
    int c = threadIdx.x;
    float inv  = 1.f / (float)P_ROWS;
    float mean = g_stats1[c] * inv;
    float var  = g_stats1[128 + c] * inv - mean * mean;
    float sc   = gamma1[c] * rsqrtf(var + BN_EPS);
    g_aff1[c]       = sc;
    g_aff1[128 + c] = beta1[c] - mean * sc;
}

// ---------------- K4 ----------------
__global__ __launch_bounds__(256) void k4_reduce(const float* __restrict__ bw) {
    __shared__ float sSum[64], sSq[64];
    const int tid = threadIdx.x;
    if (tid < 64) { sSum[tid] = 0.f; sSq[tid] = 0.f; }
    __syncthreads();
    const int qd = tid & 15;
    const int al = tid >> 4;
    const int c4 = qd * 4;
    float sc1[4], sh1[4], sc2[4], sh2[4];
    #pragma unroll
    for (int e = 0; e < 4; ++e) {
        sc1[e] = g_aff1[c4 + e];       sh1[e] = g_aff1[128 + c4 + e];
        sc2[e] = g_aff1[64 + c4 + e];  sh2[e] = g_aff1[192 + c4 + e];
    }
    float lsum[4] = {0.f, 0.f, 0.f, 0.f}, lsq[4] = {0.f, 0.f, 0.f, 0.f};

    for (int n = blockIdx.x * 16 + al; n < N_ATOMS; n += gridDim.x * 16) {
        float acc[4] = {0.f, 0.f, 0.f, 0.f};
        #pragma unroll
        for (int m = 0; m < 12; m++) {
            size_t base = (size_t)(n * 12 + m) * C_DIM;
            uint2 hf = __ldcs((const uint2*)&g_Zh[base + c4]);
            uint2 hc = __ldcs((const uint2*)&g_Zh[base + 64 + c4]);
            float2 f0 = __half22float2(*(__half2*)&hf.x);
            float2 f1 = __half22float2(*(__half2*)&hf.y);
            float2 c0 = __half22float2(*(__half2*)&hc.x);
            float2 c1 = __half22float2(*(__half2*)&hc.y);
            float w  = __ldg(&bw[n * 12 + m]);
            float w2 = w * w;
            float z1[4] = { fmaf(f0.x, sc1[0], sh1[0]), fmaf(f0.y, sc1[1], sh1[1]),
                            fmaf(f1.x, sc1[2], sh1[2]), fmaf(f1.y, sc1[3], sh1[3]) };
            float z2[4] = { fmaf(c0.x, sc2[0], sh2[0]), fmaf(c0.y, sc2[1], sh2[1]),
                            fmaf(c1.x, sc2[2], sh2[2]), fmaf(c1.y, sc2[3], sh2[3]) };
            #pragma unroll
            for (int e = 0; e < 4; ++e)
                acc[e] = fmaf(w2 * sigmoid_fast(z1[e]), softplus_fast(z2[e]), acc[e]);
        }
        float4 o; o.x = acc[0]; o.y = acc[1]; o.z = acc[2]; o.w = acc[3];
        *(float4*)&g_NS[n * 64 + c4] = o;
        #pragma unroll
        for (int e = 0; e < 4; ++e) {
            lsum[e] += acc[e];
            lsq[e]  = fmaf(acc[e], acc[e], lsq[e]);
        }
    }
    #pragma unroll
    for (int e = 0; e < 4; ++e) {
        atomicAdd(&sSum[c4 + e], lsum[e]);
        atomicAdd(&sSq[c4 + e],  lsq[e]);
    }
    __syncthreads();
    if (tid < 64) {
        atomicAdd(&g_stats2[tid],      sSum[tid]);
        atomicAdd(&g_stats2[64 + tid], sSq[tid]);
    }
}

// ---------------- K5 ----------------
__global__ void k5_aff2(const float* __restrict__ gamma2,
                        const float* __restrict__ beta2) {
    int f = threadIdx.x;
    float inv  = 1.f / (float)N_ATOMS;
    float mean = g_stats2[f] * inv;
    float var  = g_stats2[64 + f] * inv - mean * mean;
    float sc   = gamma2[f] * rsqrtf(var + BN_EPS);
    g_aff2[f]      = sc;
    g_aff2[64 + f] = beta2[f] - mean * sc;
}

// ---------------- K6 ----------------
__global__ void k6_out(const float* __restrict__ atom, float* __restrict__ out) {
    int i = blockIdx.x * blockDim.x + threadIdx.x;
    if (i < N_ATOMS * F_DIM) {
        int f = i & 63;
        float x = atom[i] + fmaf(g_NS[i], g_aff2[f], g_aff2[64 + f]);
        out[i] = softplus_fast(x);
    }
}

// ---------------- launch ----------------
extern "C" void kernel_launch(void* const* d_in, const int* in_sizes, int n_in,
                              void* d_out, int out_size) {
    const float* atom   = (const float*)d_in[0];
    const float* nbr    = (const float*)d_in[1];
    const float* bw     = (const float*)d_in[2];
    const int*   idx    = (const int*)  d_in[3];
    const float* W      = (const float*)d_in[4];
    const float* b      = (const float*)d_in[5];
    const float* gamma1 = (const float*)d_in[6];
    const float* beta1  = (const float*)d_in[7];
    const float* gamma2 = (const float*)d_in[8];
    const float* beta2  = (const float*)d_in[9];
    float* out = (float*)d_out;

    cudaFuncSetAttribute(k1_hmma, cudaFuncAttributeMaxDynamicSharedMemorySize, K1_TOT);
    cudaFuncSetAttribute(k2_hmma, cudaFuncAttributeMaxDynamicSharedMemorySize, SM_TOT);

    knop<<<1, 32>>>();
    knop<<<1, 32>>>();
    knop<<<1, 32>>>();
    k1_hmma<<<444, 128, K1_TOT>>>(atom, W, b);
    k2_hmma<<<444, 128, SM_TOT>>>(nbr, idx);
    k3_aff1<<<1, 128>>>(gamma1, beta1);
    k4_reduce<<<592, 256>>>(bw);
    k5_aff2<<<1, 64>>>(gamma2, beta2);
    k6_out<<<(N_ATOMS * F_DIM + 255) / 256, 256>>>(atom, out);
}

// round 16
// speedup vs baseline: 1.8443x; 1.0459x over previous
#include <cuda_runtime.h>
#include <cuda_fp16.h>
#include <cuda_bf16.h>
#include <stdint.h>
#include <math.h>

#define N_ATOMS 100000
#define M_NBR   12
#define F_DIM   64
#define C_DIM   128
#define KW      192
#define P_ROWS  (N_ATOMS * M_NBR)  // 1200000
#define BN_EPS  1e-5f
#define NWTILES (P_ROWS / 32)      // 37500
#define NATILES (N_ATOMS / 32)     // 3125

typedef unsigned long long u64;

// ---------------- scratch ----------------
__device__ __align__(256) float  g_S [N_ATOMS * C_DIM];
__device__ __align__(256) float  g_P [N_ATOMS * C_DIM];
__device__ __align__(256) __half g_Zh[(size_t)P_ROWS * C_DIM];
__device__ __align__(256) float  g_NS[N_ATOMS * F_DIM];
__device__ __align__(256) __nv_bfloat16 g_Wh[C_DIM * 64];
__device__ __align__(256) __nv_bfloat16 g_Wl[C_DIM * 64];
__device__ float g_stats1[2 * C_DIM];
__device__ float g_stats2[2 * F_DIM];
__device__ float g_aff1 [2 * C_DIM];
__device__ float g_aff2 [2 * F_DIM];

// ---------------- helpers ----------------
__device__ __forceinline__ float tanh_fast(float x) {
    float y; asm("tanh.approx.f32 %0, %1;" : "=f"(y) : "f"(x)); return y;
}
__device__ __forceinline__ float sigmoid_fast(float x) {
    return fmaf(0.5f, tanh_fast(0.5f * x), 0.5f);
}
__device__ __forceinline__ float softplus_fast(float x) {
    return fmaxf(x, 0.f) + __logf(1.f + __expf(-fabsf(x)));
}
__device__ __forceinline__ uint32_t smem_u32(const void* p) {
    uint32_t a;
    asm("{ .reg .u64 t; cvta.to.shared.u64 t, %1; cvt.u32.u64 %0, t; }" : "=r"(a) : "l"(p));
    return a;
}
#define SWZ(b) ((b) ^ (((b) >> 3) & 0x70))

__device__ __forceinline__ void ldsm4(uint32_t* r, uint32_t addr) {
    asm volatile("ldmatrix.sync.aligned.m8n8.x4.shared.b16 {%0,%1,%2,%3}, [%4];"
        : "=r"(r[0]), "=r"(r[1]), "=r"(r[2]), "=r"(r[3]) : "r"(addr));
}
__device__ __forceinline__ void mma_bf16(float* d, const uint32_t* a, const uint32_t* b) {
    asm volatile("mma.sync.aligned.m16n8k16.row.col.f32.bf16.bf16.f32 "
        "{%0,%1,%2,%3}, {%4,%5,%6,%7}, {%8,%9}, {%0,%1,%2,%3};"
        : "+f"(d[0]), "+f"(d[1]), "+f"(d[2]), "+f"(d[3])
        : "r"(a[0]), "r"(a[1]), "r"(a[2]), "r"(a[3]), "r"(b[0]), "r"(b[1]));
}
__device__ __forceinline__ void split_bf16x2(float x, float y,
                                             uint32_t& hi, uint32_t& lo) {
    __nv_bfloat162 h, l;
    h.x = __float2bfloat16(x); h.y = __float2bfloat16(y);
    l.x = __float2bfloat16(x - __bfloat162float(h.x));
    l.y = __float2bfloat16(y - __bfloat162float(h.y));
    hi = *(uint32_t*)&h; lo = *(uint32_t*)&l;
}

__global__ void knop() {}

// ============ K1: HMMA S,P precompute (full hi/lo split) ============
#define K1_B_HI 0
#define K1_B_LO 32768
#define K1_A    65536
#define K1_TOT  98304

__global__ __launch_bounds__(128, 2) void k1_hmma(
        const float* __restrict__ atom, const float* __restrict__ W,
        const float* __restrict__ b) {
    extern __shared__ __align__(1024) unsigned char SB[];
    const uint32_t sbase = smem_u32(SB);
    const int tid = threadIdx.x, wid = tid >> 5, lane = tid & 31;

    if (blockIdx.x == 0) {
        if (tid < 128) { g_stats1[tid] = 0.f; g_stats1[128 + tid] = 0.f; }
        if (tid < 64)  { g_stats2[tid] = 0.f; g_stats2[64  + tid] = 0.f; }
        for (int i = tid; i < C_DIM * 64; i += 128) {
            int c = i >> 6, k = i & 63;
            float x = W[c * KW + 128 + k];
            __nv_bfloat16 hi = __float2bfloat16(x);
            __nv_bfloat16 lo = __float2bfloat16(x - __bfloat162float(hi));
            g_Wh[i] = hi; g_Wl[i] = lo;
        }
    }

    for (int i = tid; i < 256 * 8; i += 128) {
        int c = i >> 3, u = i & 7;
        const float* src = (c < 128) ? &W[c * KW + u * 8]
                                     : &W[(c - 128) * KW + 64 + u * 8];
        float4 va = *(const float4*)src;
        float4 vb = *(const float4*)(src + 4);
        uint4 hi4, lo4;
        split_bf16x2(va.x, va.y, hi4.x, lo4.x);
        split_bf16x2(va.z, va.w, hi4.y, lo4.y);
        split_bf16x2(vb.x, vb.y, hi4.z, lo4.z);
        split_bf16x2(vb.z, vb.w, hi4.w, lo4.w);
        uint32_t sw = SWZ((uint32_t)(c * 128 + u * 16));
        *(uint4*)(SB + K1_B_HI + sw) = hi4;
        *(uint4*)(SB + K1_B_LO + sw) = lo4;
    }
    __syncthreads();

    const int g    = lane >> 2, cq = lane & 3;
    const int sel  = lane >> 3;
    const int rsel = ((sel & 1) << 3) | (lane & 7);
    const int ksel = (sel >> 1) << 4;
    const int nsel = ((sel >> 1) << 3) | (lane & 7);
    const int kselB = (sel & 1) << 4;
    unsigned char* aW = SB + K1_A + (wid << 13);
    const uint32_t aBase = sbase + K1_A + (wid << 13);

    for (int wt = blockIdx.x * 4 + wid; wt < NATILES; wt += gridDim.x * 4) {
        const int n0 = wt * 32;

        #pragma unroll
        for (int pass = 0; pass < 4; ++pass) {
            int r  = pass * 8 + g;
            int c0 = cq * 16;
            #pragma unroll
            for (int q = 0; q < 4; ++q) {
                float4 v = *(const float4*)&atom[(size_t)(n0 + r) * 64 + c0 + q * 4];
                uint2 sh, sl;
                split_bf16x2(v.x, v.y, sh.x, sl.x);
                split_bf16x2(v.z, v.w, sh.y, sl.y);
                uint32_t sw = SWZ((uint32_t)(r * 128 + (c0 + q * 4) * 2));
                *(uint2*)(aW + sw)        = sh;
                *(uint2*)(aW + 4096 + sw) = sl;
            }
        }
        __syncwarp();

        #pragma unroll
        for (int chunk = 0; chunk < 4; ++chunk) {
            float acc[2][8][4];
            #pragma unroll
            for (int mf = 0; mf < 2; ++mf)
                #pragma unroll
                for (int nf = 0; nf < 8; ++nf)
                    #pragma unroll
                    for (int e = 0; e < 4; ++e) acc[mf][nf][e] = 0.f;

            #pragma unroll
            for (int ks = 0; ks < 4; ++ks) {
                uint32_t Ah[2][4], Al[2][4];
                #pragma unroll
                for (int mf = 0; mf < 2; ++mf) {
                    uint32_t byteA = (uint32_t)((mf * 16 + rsel) * 128 + ks * 32 + ksel);
                    ldsm4(Ah[mf], aBase + SWZ(byteA));
                    ldsm4(Al[mf], aBase + 4096 + SWZ(byteA));
                }
                #pragma unroll
                for (int q = 0; q < 4; ++q) {
                    uint32_t byteB = (uint32_t)((chunk * 64 + q * 16 + nsel) * 128 + ks * 32 + kselB);
                    uint32_t Bh[4], Bl[4];
                    ldsm4(Bh, sbase + K1_B_HI + SWZ(byteB));
                    ldsm4(Bl, sbase + K1_B_LO + SWZ(byteB));
                    #pragma unroll
                    for (int mf = 0; mf < 2; ++mf) {
                        mma_bf16(acc[mf][q*2],   Ah[mf], Bh);
                        mma_bf16(acc[mf][q*2],   Ah[mf], Bl);
                        mma_bf16(acc[mf][q*2],   Al[mf], Bh);
                        mma_bf16(acc[mf][q*2+1], Ah[mf], Bh + 2);
                        mma_bf16(acc[mf][q*2+1], Ah[mf], Bl + 2);
                        mma_bf16(acc[mf][q*2+1], Al[mf], Bh + 2);
                    }
                }
            }

            float* dst = (chunk < 2) ? g_S : g_P;
            const int cbase = (chunk & 1) * 64;
            #pragma unroll
            for (int nf = 0; nf < 8; ++nf) {
                int c = cbase + nf * 8 + cq * 2;
                float b0 = 0.f, b1 = 0.f;
                if (chunk < 2) {
                    float2 bv = *(const float2*)&b[c];
                    b0 = bv.x; b1 = bv.y;
                }
                #pragma unroll
                for (int mf = 0; mf < 2; ++mf)
                    #pragma unroll
                    for (int rr = 0; rr < 2; ++rr) {
                        int n = n0 + mf * 16 + rr * 8 + g;
                        float2 o;
                        o.x = acc[mf][nf][rr*2]   + b0;
                        o.y = acc[mf][nf][rr*2+1] + b1;
                        *(float2*)&dst[(size_t)n * C_DIM + c] = o;
                    }
            }
        }
        __syncwarp();
    }
}

// k2 smem layout (dynamic, 48KB): B hi only
#define SM_B_HI 0
#define SM_A_HI 16384          // + wid*4096
#define SM_E    32768          // + wid*4096
#define SM_TOT  49152

// ---------------- K2: HMMA (A-hi x B-hi) + fp16 E + gather + BN1 stats -----
__global__ __launch_bounds__(128, 3) void k2_hmma(
        const float* __restrict__ nbr, const int* __restrict__ idx) {
    extern __shared__ __align__(1024) unsigned char SB[];
    const uint32_t sbase = smem_u32(SB);
    const int tid = threadIdx.x, wid = tid >> 5, lane = tid & 31;

    for (int i = tid; i < 128 * 8; i += 128) {
        int c = i >> 3, u = i & 7;
        uint32_t sw = SWZ((uint32_t)(c * 128 + u * 16));
        *(uint4*)(SB + SM_B_HI + sw) = *(const uint4*)&g_Wh[c * 64 + u * 8];
    }
    __syncthreads();

    const int g    = lane >> 2, cq = lane & 3;
    const int sel  = lane >> 3;
    const int rsel = ((sel & 1) << 3) | (lane & 7);
    const int ksel = (sel >> 1) << 4;
    const int nsel = ((sel >> 1) << 3) | (lane & 7);
    const int kselB = (sel & 1) << 4;
    unsigned char* aHi = SB + SM_A_HI + (wid << 12);
    const uint32_t aBaseHi = sbase + SM_A_HI + (wid << 12);
    const uint32_t eBase   = sbase + SM_E    + (wid << 12);

    float lsum[2][16], lsq[2][16];
    #pragma unroll
    for (int h = 0; h < 2; ++h)
        #pragma unroll
        for (int i = 0; i < 16; ++i) { lsum[h][i] = 0.f; lsq[h][i] = 0.f; }

    for (int wt = blockIdx.x * 4 + wid; wt < NWTILES; wt += gridDim.x * 4) {
        const int p0 = wt * 32;

        #pragma unroll
        for (int pass = 0; pass < 4; ++pass) {
            int r  = pass * 8 + g;
            int c0 = cq * 16;
            #pragma unroll
            for (int q = 0; q < 4; ++q) {
                float4 v = __ldcs((const float4*)&nbr[(size_t)(p0 + r) * 64 + c0 + q * 4]);
                __nv_bfloat162 h0, h1;
                h0.x = __float2bfloat16(v.x); h0.y = __float2bfloat16(v.y);
                h1.x = __float2bfloat16(v.z); h1.y = __float2bfloat16(v.w);
                uint32_t sw = SWZ((uint32_t)(r * 128 + (c0 + q * 4) * 2));
                uint2 sh;
                sh.x = *(uint32_t*)&h0; sh.y = *(uint32_t*)&h1;
                *(uint2*)(aHi + sw) = sh;
            }
        }
        __syncwarp();

        uint32_t Af[4][2][4];
        #pragma unroll
        for (int ks = 0; ks < 4; ++ks)
            #pragma unroll
            for (int mf = 0; mf < 2; ++mf) {
                uint32_t byteA = (uint32_t)((mf * 16 + rsel) * 128 + ks * 32 + ksel);
                ldsm4(Af[ks][mf], aBaseHi + SWZ(byteA));
            }

        #pragma unroll
        for (int h = 0; h < 2; ++h) {
            float acc[2][8][4];
            #pragma unroll
            for (int mf = 0; mf < 2; ++mf)
                #pragma unroll
                for (int nf = 0; nf < 8; ++nf)
                    #pragma unroll
                    for (int e = 0; e < 4; ++e) acc[mf][nf][e] = 0.f;

            #pragma unroll
            for (int ks = 0; ks < 4; ++ks) {
                #pragma unroll
                for (int q = 0; q < 4; ++q) {
                    uint32_t byteB = (uint32_t)((h * 64 + q * 16 + nsel) * 128 + ks * 32 + kselB);
                    uint32_t Bh[4];
                    ldsm4(Bh, sbase + SM_B_HI + SWZ(byteB));
                    #pragma unroll
                    for (int mf = 0; mf < 2; ++mf) {
                        mma_bf16(acc[mf][q*2],   Af[ks][mf], Bh);
                        mma_bf16(acc[mf][q*2+1], Af[ks][mf], Bh + 2);
                    }
                }
            }

            #pragma unroll
            for (int mf = 0; mf < 2; ++mf)
                #pragma unroll
                for (int nf = 0; nf < 8; ++nf)
                    #pragma unroll
                    for (int rr = 0; rr < 2; ++rr) {
                        int r = mf * 16 + rr * 8 + g;
                        int c = nf * 8 + cq * 2;
                        __half2 hv = __floats2half2_rn(acc[mf][nf][rr*2], acc[mf][nf][rr*2+1]);
                        uint32_t byte = ((uint32_t)c * 2) ^ (((uint32_t)r & 7) << 4);
                        uint32_t addr = eBase + (uint32_t)r * 128 + byte;
                        asm volatile("st.shared.b32 [%0], %1;" ::
                            "r"(addr), "r"(*(uint32_t*)&hv));
                    }
            __syncwarp();

            #pragma unroll
            for (int pass = 0; pass < 4; ++pass) {
                int r = pass * 8 + g;
                int p = p0 + r;
                int n = p / 12;
                int j = __ldg(&idx[p]);
                int cpart = cq * 16;
                float z[16];
                #pragma unroll
                for (int half16 = 0; half16 < 2; ++half16) {
                    uint32_t byte = (((uint32_t)(cpart + half16 * 8) * 2)) ^ (((uint32_t)r & 7) << 4);
                    uint32_t a0, a1, a2, a3;
                    asm volatile("ld.shared.v4.b32 {%0,%1,%2,%3}, [%4];"
                        : "=r"(a0), "=r"(a1), "=r"(a2), "=r"(a3)
                        : "r"(eBase + (uint32_t)r * 128 + byte));
                    float2 e0 = __half22float2(*(__half2*)&a0);
                    float2 e1 = __half22float2(*(__half2*)&a1);
                    float2 e2 = __half22float2(*(__half2*)&a2);
                    float2 e3 = __half22float2(*(__half2*)&a3);
                    float4 s0 = *(const float4*)&g_S[(size_t)n * C_DIM + h * 64 + cpart + half16 * 8];
                    float4 s1 = *(const float4*)&g_S[(size_t)n * C_DIM + h * 64 + cpart + half16 * 8 + 4];
                    float4 p0v = *(const float4*)&g_P[(size_t)j * C_DIM + h * 64 + cpart + half16 * 8];
                    float4 p1v = *(const float4*)&g_P[(size_t)j * C_DIM + h * 64 + cpart + half16 * 8 + 4];
                    int o = half16 * 8;
                    z[o+0] = e0.x + s0.x + p0v.x;  z[o+1] = e0.y + s0.y + p0v.y;
                    z[o+2] = e1.x + s0.z + p0v.z;  z[o+3] = e1.y + s0.w + p0v.w;
                    z[o+4] = e2.x + s1.x + p1v.x;  z[o+5] = e2.y + s1.y + p1v.y;
                    z[o+6] = e3.x + s1.z + p1v.z;  z[o+7] = e3.y + s1.w + p1v.w;
                }
                #pragma unroll
                for (int e = 0; e < 16; ++e) {
                    lsum[h][e] += z[e];
                    lsq[h][e]  = fmaf(z[e], z[e], lsq[h][e]);
                }
                uint4 st0, st1;
                {
                    __half2 a0 = __floats2half2_rn(z[0],  z[1]);
                    __half2 a1 = __floats2half2_rn(z[2],  z[3]);
                    __half2 a2 = __floats2half2_rn(z[4],  z[5]);
                    __half2 a3 = __floats2half2_rn(z[6],  z[7]);
                    __half2 a4 = __floats2half2_rn(z[8],  z[9]);
                    __half2 a5 = __floats2half2_rn(z[10], z[11]);
                    __half2 a6 = __floats2half2_rn(z[12], z[13]);
                    __half2 a7 = __floats2half2_rn(z[14], z[15]);
                    st0.x = *(uint32_t*)&a0; st0.y = *(uint32_t*)&a1;
                    st0.z = *(uint32_t*)&a2; st0.w = *(uint32_t*)&a3;
                    st1.x = *(uint32_t*)&a4; st1.y = *(uint32_t*)&a5;
                    st1.z = *(uint32_t*)&a6; st1.w = *(uint32_t*)&a7;
                }
                __stcs((uint4*)&g_Zh[(size_t)p * C_DIM + h * 64 + cpart],     st0);
                __stcs((uint4*)&g_Zh[(size_t)p * C_DIM + h * 64 + cpart + 8], st1);
            }
            __syncwarp();
        }
    }

    __syncthreads();
    float* st = (float*)SB;
    for (int i = tid; i < 512; i += 128) st[i] = 0.f;
    __syncthreads();
    #pragma unroll
    for (int h = 0; h < 2; ++h)
        #pragma unroll
        for (int e = 0; e < 16; ++e) {
            int ch = h * 64 + cq * 16 + e;
            atomicAdd(&st[ch],       lsum[h][e]);
            atomicAdd(&st[256 + ch], lsq[h][e]);
        }
    __syncthreads();
    if (tid < 128) {
        atomicAdd(&g_stats1[tid],       st[tid]);
        atomicAdd(&g_stats1[128 + tid], st[256 + tid]);
    }
}

// ---------------- K3 ----------------
__global__ void k3_aff1(const float* __restrict__ gamma1,
                        const float* __restrict__ beta1) {
    int c = threadIdx.x;
    float inv  = 1.f / (float)P_ROWS;
    float mean = g_stats1[c] * inv;
    float var  = g_stats1[128 + c] * inv - mean * mean;
    float sc   = gamma1[c] * rsqrtf(var + BN_EPS);
    g_aff1[c]       = sc;
    g_aff1[128 + c] = beta1[c] - mean * sc;
}

// ---------------- K4: 8-channel threads, uint4 streaming loads -------------
__global__ __launch_bounds__(256) void k4_reduce(const float* __restrict__ bw) {
    __shared__ float sSum[64], sSq[64];
    const int tid = threadIdx.x;
    if (tid < 64) { sSum[tid] = 0.f; sSq[tid] = 0.f; }
    __syncthreads();
    const int c8 = (tid & 7) * 8;   // channels c8..c8+7
    const int al = tid >> 3;        // 32 atom lanes
    float sc1[8], sh1[8], sc2[8], sh2[8];
    #pragma unroll
    for (int e = 0; e < 8; ++e) {
        sc1[e] = g_aff1[c8 + e];       sh1[e] = g_aff1[128 + c8 + e];
        sc2[e] = g_aff1[64 + c8 + e];  sh2[e] = g_aff1[192 + c8 + e];
    }
    float lsum[8], lsq[8];
    #pragma unroll
    for (int e = 0; e < 8; ++e) { lsum[e] = 0.f; lsq[e] = 0.f; }

    for (int n = blockIdx.x * 32 + al; n < N_ATOMS; n += gridDim.x * 32) {
        float acc[8];
        #pragma unroll
        for (int e = 0; e < 8; ++e) acc[e] = 0.f;
        #pragma unroll
        for (int m = 0; m < 12; m++) {
            size_t base = (size_t)(n * 12 + m) * C_DIM;
            uint4 hf = __ldcs((const uint4*)&g_Zh[base + c8]);
            uint4 hc = __ldcs((const uint4*)&g_Zh[base + 64 + c8]);
            float w  = __ldg(&bw[n * 12 + m]);
            float w2 = w * w;
            float2 f0 = __half22float2(*(__half2*)&hf.x);
            float2 f1 = __half22float2(*(__half2*)&hf.y);
            float2 f2 = __half22float2(*(__half2*)&hf.z);
            float2 f3 = __half22float2(*(__half2*)&hf.w);
            float2 c0 = __half22float2(*(__half2*)&hc.x);
            float2 c1 = __half22float2(*(__half2*)&hc.y);
            float2 c2 = __half22float2(*(__half2*)&hc.z);
            float2 c3 = __half22float2(*(__half2*)&hc.w);
            float zf[8] = { f0.x, f0.y, f1.x, f1.y, f2.x, f2.y, f3.x, f3.y };
            float zc[8] = { c0.x, c0.y, c1.x, c1.y, c2.x, c2.y, c3.x, c3.y };
            #pragma unroll
            for (int e = 0; e < 8; ++e) {
                float z1 = fmaf(zf[e], sc1[e], sh1[e]);
                float z2 = fmaf(zc[e], sc2[e], sh2[e]);
                acc[e] = fmaf(w2 * sigmoid_fast(z1), softplus_fast(z2), acc[e]);
            }
        }
        float4 o0, o1;
        o0.x = acc[0]; o0.y = acc[1]; o0.z = acc[2]; o0.w = acc[3];
        o1.x = acc[4]; o1.y = acc[5]; o1.z = acc[6]; o1.w = acc[7];
        *(float4*)&g_NS[n * 64 + c8]     = o0;
        *(float4*)&g_NS[n * 64 + c8 + 4] = o1;
        #pragma unroll
        for (int e = 0; e < 8; ++e) {
            lsum[e] += acc[e];
            lsq[e]  = fmaf(acc[e], acc[e], lsq[e]);
        }
    }
    #pragma unroll
    for (int e = 0; e < 8; ++e) {
        atomicAdd(&sSum[c8 + e], lsum[e]);
        atomicAdd(&sSq[c8 + e],  lsq[e]);
    }
    __syncthreads();
    if (tid < 64) {
        atomicAdd(&g_stats2[tid],      sSum[tid]);
        atomicAdd(&g_stats2[64 + tid], sSq[tid]);
    }
}

// ---------------- K5 ----------------
__global__ void k5_aff2(const float* __restrict__ gamma2,
                        const float* __restrict__ beta2) {
    int f = threadIdx.x;
    float inv  = 1.f / (float)N_ATOMS;
    float mean = g_stats2[f] * inv;
    float var  = g_stats2[64 + f] * inv - mean * mean;
    float sc   = gamma2[f] * rsqrtf(var + BN_EPS);
    g_aff2[f]      = sc;
    g_aff2[64 + f] = beta2[f] - mean * sc;
}

// ---------------- K6 ----------------
__global__ void k6_out(const float* __restrict__ atom, float* __restrict__ out) {
    int i = blockIdx.x * blockDim.x + threadIdx.x;
    if (i < N_ATOMS * F_DIM) {
        int f = i & 63;
        float x = atom[i] + fmaf(g_NS[i], g_aff2[f], g_aff2[64 + f]);
        out[i] = softplus_fast(x);
    }
}

// ---------------- launch ----------------
extern "C" void kernel_launch(void* const* d_in, const int* in_sizes, int n_in,
                              void* d_out, int out_size) {
    const float* atom   = (const float*)d_in[0];
    const float* nbr    = (const float*)d_in[1];
    const float* bw     = (const float*)d_in[2];
    const int*   idx    = (const int*)  d_in[3];
    const float* W      = (const float*)d_in[4];
    const float* b      = (const float*)d_in[5];
    const float* gamma1 = (const float*)d_in[6];
    const float* beta1  = (const float*)d_in[7];
    const float* gamma2 = (const float*)d_in[8];
    const float* beta2  = (const float*)d_in[9];
    float* out = (float*)d_out;

    cudaFuncSetAttribute(k1_hmma, cudaFuncAttributeMaxDynamicSharedMemorySize, K1_TOT);
    cudaFuncSetAttribute(k2_hmma, cudaFuncAttributeMaxDynamicSharedMemorySize, SM_TOT);

    knop<<<1, 32>>>();
    knop<<<1, 32>>>();
    k1_hmma<<<444, 128, K1_TOT>>>(atom, W, b);
    k2_hmma<<<444, 128, SM_TOT>>>(nbr, idx);
    k3_aff1<<<1, 128>>>(gamma1, beta1);
    k4_reduce<<<592, 256>>>(bw);
    k5_aff2<<<1, 64>>>(gamma2, beta2);
    k6_out<<<(N_ATOMS * F_DIM + 255) / 256, 256>>>(atom, out);
}